// round 14
// baseline (speedup 1.0000x reference)
#include <cuda_runtime.h>
#include <cuda_bf16.h>
#include <math.h>
#include <cstdint>

#define N_QP   25000
#define N_REFP 50000
#define NEDGE  400000
#define C0     128
#define C1     256
#define BN_EPS 1e-5f

// ---------------- scratch ----------------
__device__ float d_w[NEDGE];
__device__ float d_wsum[N_QP];
__device__ int   d_deg[N_QP];
__device__ int   d_cursor[N_QP];
__device__ int   d_rowstart[N_QP + 1];
__device__ int   d_rsorted[NEDGE];
__device__ float d_wsorted[NEDGE];
__device__ float d_Y1[(size_t)N_REFP * C0];
__device__ float d_S [(size_t)N_QP * C0];
__device__ float d_Y2[(size_t)N_QP * C1];
__device__ float d_Y3[(size_t)N_QP * C1];
__device__ float d_partial[600 * 1024];      // region A @0, region B @400*1024
__device__ float d_bn[4][2][256];
__device__ unsigned int d_ctr[4];            // self-resetting GEMM tickets
__device__ __nv_bfloat16 d_refH[(size_t)N_REFP * C0], d_refL[(size_t)N_REFP * C0];
__device__ __nv_bfloat16 d_qH[(size_t)N_QP * C0],     d_qL[(size_t)N_QP * C0];
__device__ __nv_bfloat16 d_X0H[(size_t)N_QP * C0],    d_X0L[(size_t)N_QP * C0];
__device__ __nv_bfloat16 d_X1H[(size_t)N_QP * C1],    d_X1L[(size_t)N_QP * C1];
__device__ __nv_bfloat16 d_Wf0H[C0 * C0], d_Wf0L[C0 * C0];
__device__ __nv_bfloat16 d_Ws0H[C0 * C0], d_Ws0L[C0 * C0];
__device__ __nv_bfloat16 d_W1H[C0 * C1],  d_W1L[C0 * C1];
__device__ __nv_bfloat16 d_W2H[C1 * C1],  d_W2L[C1 * C1];

// ======================= helpers =======================
__device__ __forceinline__ uint32_t smem_u32(const void* p) {
    uint32_t a;
    asm("{ .reg .u64 t; cvta.to.shared.u64 t, %1; cvt.u32.u64 %0, t; }" : "=r"(a) : "l"(p));
    return a;
}
__device__ __forceinline__ void ldsm_x4(uint32_t& r0, uint32_t& r1, uint32_t& r2, uint32_t& r3,
                                        uint32_t addr) {
    asm volatile("ldmatrix.sync.aligned.m8n8.x4.shared.b16 {%0,%1,%2,%3}, [%4];"
                 : "=r"(r0), "=r"(r1), "=r"(r2), "=r"(r3) : "r"(addr));
}
__device__ __forceinline__ void ldsm_x4_t(uint32_t& r0, uint32_t& r1, uint32_t& r2, uint32_t& r3,
                                          uint32_t addr) {
    asm volatile("ldmatrix.sync.aligned.m8n8.x4.trans.shared.b16 {%0,%1,%2,%3}, [%4];"
                 : "=r"(r0), "=r"(r1), "=r"(r2), "=r"(r3) : "r"(addr));
}
__device__ __forceinline__ void mma_bf16(float* c, const uint32_t* a, const uint32_t* b) {
    asm volatile(
        "mma.sync.aligned.m16n8k16.row.col.f32.bf16.bf16.f32 "
        "{%0,%1,%2,%3}, {%4,%5,%6,%7}, {%8,%9}, {%0,%1,%2,%3};"
        : "+f"(c[0]), "+f"(c[1]), "+f"(c[2]), "+f"(c[3])
        : "r"(a[0]), "r"(a[1]), "r"(a[2]), "r"(a[3]), "r"(b[0]), "r"(b[1]));
}
__device__ __forceinline__ void cpa16(uint32_t dst, const void* src, int valid) {
    asm volatile("cp.async.cg.shared.global [%0], [%1], 16, %2;"
                 :: "r"(dst), "l"(src), "r"(valid ? 16 : 0) : "memory");
}
__device__ __forceinline__ void split2(float v, uint16_t& h, uint16_t& l) {
    __nv_bfloat16 bh = __float2bfloat16(v);
    __nv_bfloat16 bl = __float2bfloat16(v - __bfloat162float(bh));
    h = *(uint16_t*)&bh; l = *(uint16_t*)&bl;
}
__device__ __forceinline__ void split4_store(const float* X, uint16_t* H, uint16_t* L, int q) {
    float4 v = *(const float4*)(X + q * 4);
    uint16_t h[4], l[4];
    split2(v.x, h[0], l[0]); split2(v.y, h[1], l[1]);
    split2(v.z, h[2], l[2]); split2(v.w, h[3], l[3]);
    *(uint2*)(H + q * 4) = make_uint2(h[0] | ((uint32_t)h[1] << 16), h[2] | ((uint32_t)h[3] << 16));
    *(uint2*)(L + q * 4) = make_uint2(l[0] | ((uint32_t)l[1] << 16), l[2] | ((uint32_t)l[3] << 16));
}

// ---------------- split kernels (R12 layout) ----------------
#define QR  1600000
#define QQ  800000
#define QW0 4096
#define QW1 4096
#define QW2 8192
#define QW3 16384
#define QA_TOT (QR + QW0)
#define QB_TOT (QQ + QW1 + QW2 + QW3)
__global__ void k_split_a(const float* __restrict__ ref, const float* __restrict__ Wf0) {
    int i = blockIdx.x * blockDim.x + threadIdx.x;
    if (i >= QA_TOT) return;
    if (i < QR) { split4_store(ref, (uint16_t*)d_refH, (uint16_t*)d_refL, i); return; }
    i -= QR;
    split4_store(Wf0, (uint16_t*)d_Wf0H, (uint16_t*)d_Wf0L, i);
}
__global__ void k_split_b(const float* __restrict__ qf, const float* __restrict__ Ws0,
                          const float* __restrict__ W1, const float* __restrict__ W2) {
    int i = blockIdx.x * blockDim.x + threadIdx.x;
    if (i >= QB_TOT) return;
    if (i < QQ) { split4_store(qf, (uint16_t*)d_qH, (uint16_t*)d_qL, i); return; }
    i -= QQ;
    if (i < QW1) { split4_store(Ws0, (uint16_t*)d_Ws0H, (uint16_t*)d_Ws0L, i); return; }
    i -= QW1;
    if (i < QW2) { split4_store(W1, (uint16_t*)d_W1H, (uint16_t*)d_W1L, i); return; }
    i -= QW2;
    split4_store(W2, (uint16_t*)d_W2H, (uint16_t*)d_W2L, i);
}

// ---------------- init ----------------
__global__ void k_init() {
    int i = blockIdx.x * blockDim.x + threadIdx.x;
    if (i >= N_QP / 4 + 1) return;
    if (i * 4 + 3 < N_QP) {
        *(float4*)(d_wsum + i * 4) = make_float4(0.f, 0.f, 0.f, 0.f);
        *(int4*)(d_deg + i * 4) = make_int4(0, 0, 0, 0);
        *(int4*)(d_cursor + i * 4) = make_int4(0, 0, 0, 0);
    } else {
        for (int j = i * 4; j < N_QP; j++) { d_wsum[j] = 0.f; d_deg[j] = 0; d_cursor[j] = 0; }
    }
}

// ---------------- pipelined split-bf16 GEMM + fused column stats + fused BN-finalize ----------------
// Last CTA (ticket) reduces partials -> bna/bnc, then resets counter (graph-safe).
#define KC 32
#define A_STRIDE 40
#define B_STRIDE 136
__global__ __launch_bounds__(256, 2)
void k_mma(const __nv_bfloat16* __restrict__ Ah, const __nv_bfloat16* __restrict__ Al,
           const __nv_bfloat16* __restrict__ Bh, const __nv_bfloat16* __restrict__ Bl,
           float* __restrict__ C, float* __restrict__ partial, int M, int N, int K,
           const float* __restrict__ gam, const float* __restrict__ bet,
           float* __restrict__ bna, float* __restrict__ bnc, unsigned int* __restrict__ ctr) {
    __shared__ __align__(16) uint16_t sA[2][128 * A_STRIDE];
    __shared__ __align__(16) uint16_t sB[2][KC * B_STRIDE];
    __shared__ float sS[8][32], sS2[8][32];
    __shared__ unsigned int sTicket;
    int tid = threadIdx.x, wid = tid >> 5, lane = tid & 31;
    int bm = blockIdx.x * 128, bn = blockIdx.y * 128;
    int wm = (wid & 1) * 64, wn = (wid >> 1) * 32;
    int mat = lane >> 3, r = lane & 7;
    int kpt = K >> 5;
    int nst = 3 * kpt;

    float acc[4][4][4];
    #pragma unroll
    for (int i = 0; i < 4; i++)
        #pragma unroll
        for (int j = 0; j < 4; j++)
            #pragma unroll
            for (int v = 0; v < 4; v++) acc[i][j][v] = 0.f;

    uint32_t aBase[2] = { smem_u32(sA[0]), smem_u32(sA[1]) };
    uint32_t bBase[2] = { smem_u32(sB[0]), smem_u32(sB[1]) };

    auto issueA = [&](const __nv_bfloat16* Ap, int koff, int slot) {
        #pragma unroll
        for (int i = 0; i < 2; i++) {
            int seg = i * 256 + tid;
            int row = seg >> 2, cs = (seg & 3) << 3;
            cpa16(aBase[slot] + (row * A_STRIDE + cs) * 2,
                  Ap + (size_t)(bm + row) * K + koff + cs, (bm + row) < M);
        }
    };
    auto issueB = [&](const __nv_bfloat16* Bp, int koff, int slot) {
        #pragma unroll
        for (int i = 0; i < 2; i++) {
            int seg = i * 256 + tid;
            int row = seg >> 4, cs = (seg & 15) << 3;
            cpa16(bBase[slot] + (row * B_STRIDE + cs) * 2,
                  Bp + (size_t)(koff + row) * N + bn + cs, 1);
        }
    };

    issueA(Ah, 0, 0);
    issueB(Bh, 0, 0);
    asm volatile("cp.async.commit_group;" ::: "memory");

    for (int s = 0; s < nst; s++) {
        int k = s / 3, t = s - 3 * k;
        if (s + 1 < nst) {
            int s1 = s + 1, k1 = s1 / 3, t1 = s1 - 3 * k1;
            if (t1 == 0) {
                issueA(Ah, k1 << 5, 0);
                issueB(Bh, k1 << 5, k1 & 1);
            } else if (t1 == 1) {
                issueB(Bl, k1 << 5, (k1 & 1) ^ 1);
            } else {
                issueA(Al, k1 << 5, 1);
            }
            asm volatile("cp.async.commit_group;" ::: "memory");
            asm volatile("cp.async.wait_group 1;" ::: "memory");
        } else {
            asm volatile("cp.async.wait_group 0;" ::: "memory");
        }
        __syncthreads();
        int as = (t == 2) ? 1 : 0;
        int bs = (t == 1) ? ((k & 1) ^ 1) : (k & 1);
        #pragma unroll
        for (int ks = 0; ks < KC / 16; ks++) {
            uint32_t a[4][4], b[4][2];
            #pragma unroll
            for (int mt = 0; mt < 4; mt++) {
                int mrow = wm + mt * 16 + (mat & 1) * 8 + r;
                int kcol = ks * 16 + (mat >> 1) * 8;
                ldsm_x4(a[mt][0], a[mt][1], a[mt][2], a[mt][3],
                        aBase[as] + (mrow * A_STRIDE + kcol) * 2);
            }
            #pragma unroll
            for (int nt = 0; nt < 2; nt++) {
                int krow = ks * 16 + (mat & 1) * 8 + r;
                int ncol = wn + nt * 16 + (mat >> 1) * 8;
                ldsm_x4_t(b[nt * 2][0], b[nt * 2][1], b[nt * 2 + 1][0], b[nt * 2 + 1][1],
                          bBase[bs] + (krow * B_STRIDE + ncol) * 2);
            }
            #pragma unroll
            for (int mt = 0; mt < 4; mt++)
                #pragma unroll
                for (int nt = 0; nt < 4; nt++)
                    mma_bf16(acc[mt][nt], a[mt], b[nt]);
        }
        __syncthreads();
    }

    int g = lane >> 2, tg = lane & 3;
    #pragma unroll
    for (int mt = 0; mt < 4; mt++) {
        #pragma unroll
        for (int nt = 0; nt < 4; nt++) {
            int row0 = bm + wm + mt * 16 + g;
            int col = bn + wn + nt * 8 + tg * 2;
            if (row0 < M) {
                C[(size_t)row0 * N + col] = acc[mt][nt][0];
                C[(size_t)row0 * N + col + 1] = acc[mt][nt][1];
            }
            int row1 = row0 + 8;
            if (row1 < M) {
                C[(size_t)row1 * N + col] = acc[mt][nt][2];
                C[(size_t)row1 * N + col + 1] = acc[mt][nt][3];
            }
        }
    }

    // fused column stats (rows >= M contributed exact zeros)
    #pragma unroll
    for (int nt = 0; nt < 4; nt++) {
        #pragma unroll
        for (int p = 0; p < 2; p++) {
            float ss = 0.f, qq = 0.f;
            #pragma unroll
            for (int mt = 0; mt < 4; mt++) {
                float a0 = acc[mt][nt][p], a1 = acc[mt][nt][p + 2];
                ss += a0 + a1;
                qq += a0 * a0 + a1 * a1;
            }
            #pragma unroll
            for (int off = 16; off >= 4; off >>= 1) {
                ss += __shfl_down_sync(0xffffffff, ss, off);
                qq += __shfl_down_sync(0xffffffff, qq, off);
            }
            if (g == 0) {
                sS[wid][nt * 8 + tg * 2 + p] = ss;
                sS2[wid][nt * 8 + tg * 2 + p] = qq;
            }
        }
    }
    __syncthreads();
    if (tid < 128) {
        int w0 = (tid >> 5) * 2, lc = tid & 31;
        partial[blockIdx.x * 1024 + bn + tid] = sS[w0][lc] + sS[w0 + 1][lc];
        partial[blockIdx.x * 1024 + 512 + bn + tid] = sS2[w0][lc] + sS2[w0 + 1][lc];
    }

    // fused BN-finalize in the last CTA (threadFenceReduction pattern)
    __threadfence();
    unsigned int total = gridDim.x * gridDim.y;
    if (tid == 0) sTicket = atomicAdd(ctr, 1u);
    __syncthreads();
    if (sTicket == total - 1) {
        int nblk = gridDim.x;
        for (int c = tid; c < N; c += 256) {
            float s = 0.f, s2 = 0.f;
            for (int bx = 0; bx < nblk; bx++) {
                s += partial[bx * 1024 + c];
                s2 += partial[bx * 1024 + 512 + c];
            }
            float m = s / (float)M;
            float v = s2 / (float)M - m * m;
            float a = gam[c] * rsqrtf(v + BN_EPS);
            bna[c] = a;
            bnc[c] = bet[c] - a * m;
        }
        __syncthreads();
        if (tid == 0) *ctr = 0u;   // self-reset: graph-replayable
    }
}

// ---------------- edge weights + degree histogram ----------------
__global__ void k_edge(const float4* __restrict__ ref_bxyz,
                       const float4* __restrict__ query_bxyz,
                       const int* __restrict__ e_ref,
                       const int* __restrict__ e_query) {
    int e = blockIdx.x * blockDim.x + threadIdx.x;
    if (e >= NEDGE) return;
    int r = e_ref[e], q = e_query[e];
    float4 rb = ref_bxyz[r];
    float4 qb = query_bxyz[q];
    float dx = rb.y - qb.y, dy = rb.z - qb.z, dz = rb.w - qb.w;
    float dist = sqrtf(dx * dx + dy * dy + dz * dz);
    float w = 1.0f / (dist + 1e-8f);
    d_w[e] = w;
    atomicAdd(&d_wsum[q], w);
    atomicAdd(&d_deg[q], 1);
}

// ---------------- single-pass scan ----------------
__global__ void k_scan() {
    __shared__ int wsum[32];
    const int CH = 25;
    int tid = threadIdx.x, lane = tid & 31, wid = tid >> 5;
    int base = tid * CH;
    int s = 0;
    #pragma unroll
    for (int i = 0; i < CH; i++) {
        int idx = base + i;
        if (idx < N_QP) s += d_deg[idx];
    }
    int v = s;
    #pragma unroll
    for (int off = 1; off < 32; off <<= 1) {
        int t = __shfl_up_sync(0xffffffff, v, off);
        if (lane >= off) v += t;
    }
    if (lane == 31) wsum[wid] = v;
    __syncthreads();
    if (wid == 0) {
        int w = wsum[lane];
        #pragma unroll
        for (int off = 1; off < 32; off <<= 1) {
            int t = __shfl_up_sync(0xffffffff, w, off);
            if (lane >= off) w += t;
        }
        wsum[lane] = w;
    }
    __syncthreads();
    int warp_excl = (wid == 0) ? 0 : wsum[wid - 1];
    int run = warp_excl + v - s;
    #pragma unroll
    for (int i = 0; i < CH; i++) {
        int idx = base + i;
        if (idx < N_QP) { d_rowstart[idx] = run; run += d_deg[idx]; }
    }
    if (base < N_QP && base + CH >= N_QP) d_rowstart[N_QP] = run;
}

// ---------------- bucket-fill ----------------
__global__ void k_fill(const int* __restrict__ e_query, const int* __restrict__ e_ref) {
    int e = blockIdx.x * blockDim.x + threadIdx.x;
    if (e >= NEDGE) return;
    int q = e_query[e];
    int pos = atomicAdd(&d_cursor[q], 1) + d_rowstart[q];
    d_rsorted[pos] = e_ref[e];
    d_wsorted[pos] = d_w[e];
}

// ---------------- fused gather + x0 ----------------
__global__ void k_gather_x0(const float* __restrict__ bna0, const float* __restrict__ bnc0,
                            const float* __restrict__ bna1, const float* __restrict__ bnc1) {
    __shared__ float sPart[4][128];
    int q = blockIdx.x;
    int tid = threadIdx.x, wid = tid >> 5, lane = tid & 31;
    int s = d_rowstart[q], t = d_rowstart[q + 1];
    float4 acc = make_float4(0.f, 0.f, 0.f, 0.f);
    for (int i = s + wid; i < t; i += 4) {
        int r = d_rsorted[i];
        float w = d_wsorted[i];
        float4 y = *(const float4*)(d_Y1 + (size_t)r * C0 + lane * 4);
        acc.x = fmaf(w, y.x, acc.x); acc.y = fmaf(w, y.y, acc.y);
        acc.z = fmaf(w, y.z, acc.z); acc.w = fmaf(w, y.w, acc.w);
    }
    sPart[wid][lane * 4 + 0] = acc.x;
    sPart[wid][lane * 4 + 1] = acc.y;
    sPart[wid][lane * 4 + 2] = acc.z;
    sPart[wid][lane * 4 + 3] = acc.w;
    __syncthreads();
    int c = tid;
    float sum = sPart[0][c] + sPart[1][c] + sPart[2][c] + sPart[3][c];
    float qf = 0.f;
    if (t > s) qf = bna0[c] * sum * (1.0f / d_wsum[q]) + bnc0[c];
    float sv = d_S[(size_t)q * C0 + c];
    float v = fmaxf(qf + bna1[c] * sv + bnc1[c], 0.f);
    uint16_t h, l;
    split2(v, h, l);
    ((uint16_t*)d_X0H)[(size_t)q * C0 + c] = h;
    ((uint16_t*)d_X0L)[(size_t)q * C0 + c] = l;
}

// ---------------- x1 = relu(a*Y + c), emit split bf16 (C=256) ----------------
__global__ void k_bnrelu_split(const float* __restrict__ Y, int n4,
                               const float* __restrict__ bna, const float* __restrict__ bnc) {
    int qd = blockIdx.x * blockDim.x + threadIdx.x;
    if (qd >= n4) return;
    int i = qd * 4;
    int c = i & 255;
    float4 y = *(float4*)(Y + i);
    float v0 = fmaxf(bna[c] * y.x + bnc[c], 0.f);
    float v1 = fmaxf(bna[c + 1] * y.y + bnc[c + 1], 0.f);
    float v2 = fmaxf(bna[c + 2] * y.z + bnc[c + 2], 0.f);
    float v3 = fmaxf(bna[c + 3] * y.w + bnc[c + 3], 0.f);
    uint16_t h[4], l[4];
    split2(v0, h[0], l[0]); split2(v1, h[1], l[1]);
    split2(v2, h[2], l[2]); split2(v3, h[3], l[3]);
    *(uint2*)((uint16_t*)d_X1H + i) = make_uint2(h[0] | ((uint32_t)h[1] << 16), h[2] | ((uint32_t)h[3] << 16));
    *(uint2*)((uint16_t*)d_X1L + i) = make_uint2(l[0] | ((uint32_t)l[1] << 16), l[2] | ((uint32_t)l[3] << 16));
}

// ---------------- out = relu(a*Y + c) fp32 (C=256) ----------------
__global__ void k_bnrelu_out(const float* __restrict__ Y, float* __restrict__ X, int n4,
                             const float* __restrict__ bna, const float* __restrict__ bnc) {
    int qd = blockIdx.x * blockDim.x + threadIdx.x;
    if (qd >= n4) return;
    int i = qd * 4;
    int c = i & 255;
    float4 y = *(float4*)(Y + i);
    float4 o;
    o.x = fmaxf(bna[c] * y.x + bnc[c], 0.f);
    o.y = fmaxf(bna[c + 1] * y.y + bnc[c + 1], 0.f);
    o.z = fmaxf(bna[c + 2] * y.z + bnc[c + 2], 0.f);
    o.w = fmaxf(bna[c + 3] * y.w + bnc[c + 3], 0.f);
    *(float4*)(X + i) = o;
}

// ---------------- launcher ----------------
extern "C" void kernel_launch(void* const* d_in, const int* in_sizes, int n_in,
                              void* d_out, int out_size) {
    const float* ref_bxyz   = (const float*)d_in[0];
    const float* ref_feat   = (const float*)d_in[1];
    const float* query_bxyz = (const float*)d_in[2];
    const float* query_feat = (const float*)d_in[3];
    const int*   e_ref      = (const int*)d_in[4];
    const int*   e_query    = (const int*)d_in[5];
    const float* Wf0   = (const float*)d_in[6];
    const float* gf0   = (const float*)d_in[7];
    const float* bf0   = (const float*)d_in[8];
    const float* Ws0   = (const float*)d_in[9];
    const float* gs0   = (const float*)d_in[10];
    const float* bs0   = (const float*)d_in[11];
    const float* W1    = (const float*)d_in[12];
    const float* g1    = (const float*)d_in[14];
    const float* beta1 = (const float*)d_in[15];
    const float* W2    = (const float*)d_in[16];
    const float* g2    = (const float*)d_in[18];
    const float* beta2 = (const float*)d_in[19];
    float* out = (float*)d_out;

    float *pY1, *pS, *pY2, *pY3, *pPart, *pBN;
    unsigned int* pCtr;
    cudaGetSymbolAddress((void**)&pY1, d_Y1);
    cudaGetSymbolAddress((void**)&pS,  d_S);
    cudaGetSymbolAddress((void**)&pY2, d_Y2);
    cudaGetSymbolAddress((void**)&pY3, d_Y3);
    cudaGetSymbolAddress((void**)&pPart, d_partial);
    cudaGetSymbolAddress((void**)&pBN, d_bn);
    cudaGetSymbolAddress((void**)&pCtr, d_ctr);
    float* pPartA = pPart;
    float* pPartB = pPart + 400 * 1024;
    float* bna0 = pBN;            float* bnc0 = pBN + 256;
    float* bna1 = pBN + 512;      float* bnc1 = pBN + 768;
    float* bna2 = pBN + 1024;     float* bnc2 = pBN + 1280;
    float* bna3 = pBN + 1536;     float* bnc3 = pBN + 1792;

    __nv_bfloat16 *pRefH, *pRefL, *pQH, *pQL, *pX0H, *pX0L, *pX1H, *pX1L;
    __nv_bfloat16 *pWf0H, *pWf0L, *pWs0H, *pWs0L, *pW1H, *pW1L, *pW2H, *pW2L;
    cudaGetSymbolAddress((void**)&pRefH, d_refH); cudaGetSymbolAddress((void**)&pRefL, d_refL);
    cudaGetSymbolAddress((void**)&pQH, d_qH);     cudaGetSymbolAddress((void**)&pQL, d_qL);
    cudaGetSymbolAddress((void**)&pX0H, d_X0H);   cudaGetSymbolAddress((void**)&pX0L, d_X0L);
    cudaGetSymbolAddress((void**)&pX1H, d_X1H);   cudaGetSymbolAddress((void**)&pX1L, d_X1L);
    cudaGetSymbolAddress((void**)&pWf0H, d_Wf0H); cudaGetSymbolAddress((void**)&pWf0L, d_Wf0L);
    cudaGetSymbolAddress((void**)&pWs0H, d_Ws0H); cudaGetSymbolAddress((void**)&pWs0L, d_Ws0L);
    cudaGetSymbolAddress((void**)&pW1H, d_W1H);   cudaGetSymbolAddress((void**)&pW1L, d_W1L);
    cudaGetSymbolAddress((void**)&pW2H, d_W2H);   cudaGetSymbolAddress((void**)&pW2L, d_W2L);

    static cudaStream_t s1 = nullptr, s2 = nullptr;
    static cudaEvent_t evStart, evEdge, evS;
    if (!s1) {
        cudaStreamCreateWithFlags(&s1, cudaStreamNonBlocking);
        cudaStreamCreateWithFlags(&s2, cudaStreamNonBlocking);
        cudaEventCreateWithFlags(&evStart, cudaEventDisableTiming);
        cudaEventCreateWithFlags(&evEdge, cudaEventDisableTiming);
        cudaEventCreateWithFlags(&evS, cudaEventDisableTiming);
    }

    cudaEventRecord(evStart, 0);

    // s1: edge preprocessing (fully independent)
    cudaStreamWaitEvent(s1, evStart, 0);
    k_init<<<(N_QP / 4 + 256) / 256, 256, 0, s1>>>();
    k_edge<<<(NEDGE + 255) / 256, 256, 0, s1>>>((const float4*)ref_bxyz,
                                                (const float4*)query_bxyz, e_ref, e_query);
    k_scan<<<1, 1024, 0, s1>>>();
    k_fill<<<(NEDGE + 255) / 256, 256, 0, s1>>>(e_query, e_ref);
    cudaEventRecord(evEdge, s1);

    // s2: other splits + skip-branch GEMM (BN fused, ctr1)
    cudaStreamWaitEvent(s2, evStart, 0);
    k_split_b<<<(QB_TOT + 255) / 256, 256, 0, s2>>>(query_feat, Ws0, W1, W2);
    {
        dim3 g((N_QP + 127) / 128, 1);
        k_mma<<<g, 256, 0, s2>>>(pQH, pQL, pWs0H, pWs0L, pS, pPartB, N_QP, C0, C0,
                                 gs0, bs0, bna1, bnc1, pCtr + 1);
    }
    cudaEventRecord(evS, s2);

    // main chain
    k_split_a<<<(QA_TOT + 255) / 256, 256>>>(ref_feat, Wf0);
    {
        dim3 g((N_REFP + 127) / 128, 1);
        k_mma<<<g, 256>>>(pRefH, pRefL, pWf0H, pWf0L, pY1, pPartA, N_REFP, C0, C0,
                          gf0, bf0, bna0, bnc0, pCtr + 0);
    }
    cudaStreamWaitEvent(0, evEdge, 0);
    cudaStreamWaitEvent(0, evS, 0);
    k_gather_x0<<<N_QP, 128>>>(bna0, bnc0, bna1, bnc1);

    {
        dim3 g((N_QP + 127) / 128, 2);
        k_mma<<<g, 256>>>(pX0H, pX0L, pW1H, pW1L, pY2, pPartA, N_QP, C1, C0,
                          g1, beta1, bna2, bnc2, pCtr + 2);
    }
    k_bnrelu_split<<<(N_QP * C1 / 4 + 255) / 256, 256>>>(pY2, N_QP * C1 / 4, bna2, bnc2);

    {
        dim3 g((N_QP + 127) / 128, 2);
        k_mma<<<g, 256>>>(pX1H, pX1L, pW2H, pW2L, pY3, pPartA, N_QP, C1, C1,
                          g2, beta2, bna3, bnc3, pCtr + 3);
    }
    k_bnrelu_out<<<(N_QP * C1 / 4 + 255) / 256, 256>>>(pY3, out, N_QP * C1 / 4, bna3, bnc3);
}

// round 15
// speedup vs baseline: 1.0069x; 1.0069x over previous
#include <cuda_runtime.h>
#include <cuda_bf16.h>
#include <math.h>
#include <cstdint>

#define N_QP   25000
#define N_REFP 50000
#define NEDGE  400000
#define C0     128
#define C1     256
#define BN_EPS 1e-5f
#define MHALF  25600                 // 200 tiles of 128
#define MREST  (N_REFP - MHALF)      // 24400 -> 191 tiles

// ---------------- scratch ----------------
__device__ float d_w[NEDGE];
__device__ float d_wsum[N_QP];
__device__ int   d_deg[N_QP];
__device__ int   d_cursor[N_QP];
__device__ int   d_rowstart[N_QP + 1];
__device__ int   d_rsorted[NEDGE];
__device__ float d_wsorted[NEDGE];
__device__ float d_Y1[(size_t)N_REFP * C0];
__device__ float d_S [(size_t)N_QP * C0];
__device__ float d_Y2[(size_t)N_QP * C1];
__device__ float d_Y3[(size_t)N_QP * C1];
__device__ float d_partial[600 * 1024];      // region A @0, region B @400*1024
__device__ float d_bn[4][2][256];
__device__ __nv_bfloat16 d_refH[(size_t)N_REFP * C0], d_refL[(size_t)N_REFP * C0];
__device__ __nv_bfloat16 d_qH[(size_t)N_QP * C0],     d_qL[(size_t)N_QP * C0];
__device__ __nv_bfloat16 d_X0H[(size_t)N_QP * C0],    d_X0L[(size_t)N_QP * C0];
__device__ __nv_bfloat16 d_X1H[(size_t)N_QP * C1],    d_X1L[(size_t)N_QP * C1];
__device__ __nv_bfloat16 d_Wf0H[C0 * C0], d_Wf0L[C0 * C0];
__device__ __nv_bfloat16 d_Ws0H[C0 * C0], d_Ws0L[C0 * C0];
__device__ __nv_bfloat16 d_W1H[C0 * C1],  d_W1L[C0 * C1];
__device__ __nv_bfloat16 d_W2H[C1 * C1],  d_W2L[C1 * C1];

// ======================= helpers =======================
__device__ __forceinline__ uint32_t smem_u32(const void* p) {
    uint32_t a;
    asm("{ .reg .u64 t; cvta.to.shared.u64 t, %1; cvt.u32.u64 %0, t; }" : "=r"(a) : "l"(p));
    return a;
}
__device__ __forceinline__ void ldsm_x4(uint32_t& r0, uint32_t& r1, uint32_t& r2, uint32_t& r3,
                                        uint32_t addr) {
    asm volatile("ldmatrix.sync.aligned.m8n8.x4.shared.b16 {%0,%1,%2,%3}, [%4];"
                 : "=r"(r0), "=r"(r1), "=r"(r2), "=r"(r3) : "r"(addr));
}
__device__ __forceinline__ void ldsm_x4_t(uint32_t& r0, uint32_t& r1, uint32_t& r2, uint32_t& r3,
                                          uint32_t addr) {
    asm volatile("ldmatrix.sync.aligned.m8n8.x4.trans.shared.b16 {%0,%1,%2,%3}, [%4];"
                 : "=r"(r0), "=r"(r1), "=r"(r2), "=r"(r3) : "r"(addr));
}
__device__ __forceinline__ void mma_bf16(float* c, const uint32_t* a, const uint32_t* b) {
    asm volatile(
        "mma.sync.aligned.m16n8k16.row.col.f32.bf16.bf16.f32 "
        "{%0,%1,%2,%3}, {%4,%5,%6,%7}, {%8,%9}, {%0,%1,%2,%3};"
        : "+f"(c[0]), "+f"(c[1]), "+f"(c[2]), "+f"(c[3])
        : "r"(a[0]), "r"(a[1]), "r"(a[2]), "r"(a[3]), "r"(b[0]), "r"(b[1]));
}
__device__ __forceinline__ void cpa16(uint32_t dst, const void* src, int valid) {
    asm volatile("cp.async.cg.shared.global [%0], [%1], 16, %2;"
                 :: "r"(dst), "l"(src), "r"(valid ? 16 : 0) : "memory");
}
__device__ __forceinline__ void split2(float v, uint16_t& h, uint16_t& l) {
    __nv_bfloat16 bh = __float2bfloat16(v);
    __nv_bfloat16 bl = __float2bfloat16(v - __bfloat162float(bh));
    h = *(uint16_t*)&bh; l = *(uint16_t*)&bl;
}
__device__ __forceinline__ void split4_store(const float* X, uint16_t* H, uint16_t* L, int q) {
    float4 v = *(const float4*)(X + (size_t)q * 4);
    uint16_t h[4], l[4];
    split2(v.x, h[0], l[0]); split2(v.y, h[1], l[1]);
    split2(v.z, h[2], l[2]); split2(v.w, h[3], l[3]);
    *(uint2*)(H + (size_t)q * 4) = make_uint2(h[0] | ((uint32_t)h[1] << 16), h[2] | ((uint32_t)h[3] << 16));
    *(uint2*)(L + (size_t)q * 4) = make_uint2(l[0] | ((uint32_t)l[1] << 16), l[2] | ((uint32_t)l[3] << 16));
}

// ---------------- split kernels ----------------
#define QR0 (MHALF * C0 / 4)         // 819200 quads (ref rows 0..MHALF)
#define QR1 (MREST * C0 / 4)         // 780800 quads (ref rows MHALF..)
#define QQ  800000
#define QW0 4096
#define QW1 4096
#define QW2 8192
#define QW3 16384
#define QA0_TOT (QR0 + QW0)
#define QB_TOT (QQ + QW1 + QW2 + QW3)
// critical path first half: ref rows [0, MHALF) + Wf0
__global__ void k_split_a0(const float* __restrict__ ref, const float* __restrict__ Wf0) {
    int i = blockIdx.x * blockDim.x + threadIdx.x;
    if (i >= QA0_TOT) return;
    if (i < QR0) { split4_store(ref, (uint16_t*)d_refH, (uint16_t*)d_refL, i); return; }
    i -= QR0;
    split4_store(Wf0, (uint16_t*)d_Wf0H, (uint16_t*)d_Wf0L, i);
}
// overlapped second half: ref rows [MHALF, N_REFP)
__global__ void k_split_a1(const float* __restrict__ ref) {
    int i = blockIdx.x * blockDim.x + threadIdx.x;
    if (i >= QR1) return;
    split4_store(ref, (uint16_t*)d_refH, (uint16_t*)d_refL, QR0 + i);
}
__global__ void k_split_b(const float* __restrict__ qf, const float* __restrict__ Ws0,
                          const float* __restrict__ W1, const float* __restrict__ W2) {
    int i = blockIdx.x * blockDim.x + threadIdx.x;
    if (i >= QB_TOT) return;
    if (i < QQ) { split4_store(qf, (uint16_t*)d_qH, (uint16_t*)d_qL, i); return; }
    i -= QQ;
    if (i < QW1) { split4_store(Ws0, (uint16_t*)d_Ws0H, (uint16_t*)d_Ws0L, i); return; }
    i -= QW1;
    if (i < QW2) { split4_store(W1, (uint16_t*)d_W1H, (uint16_t*)d_W1L, i); return; }
    i -= QW2;
    split4_store(W2, (uint16_t*)d_W2H, (uint16_t*)d_W2L, i);
}

// ---------------- init ----------------
__global__ void k_init() {
    int i = blockIdx.x * blockDim.x + threadIdx.x;
    if (i >= N_QP / 4 + 1) return;
    if (i * 4 + 3 < N_QP) {
        *(float4*)(d_wsum + i * 4) = make_float4(0.f, 0.f, 0.f, 0.f);
        *(int4*)(d_deg + i * 4) = make_int4(0, 0, 0, 0);
        *(int4*)(d_cursor + i * 4) = make_int4(0, 0, 0, 0);
    } else {
        for (int j = i * 4; j < N_QP; j++) { d_wsum[j] = 0.f; d_deg[j] = 0; d_cursor[j] = 0; }
    }
}

// ---------------- pipelined split-bf16 GEMM with fused column stats (R12-proven) ----------------
#define KC 32
#define A_STRIDE 40
#define B_STRIDE 136
__global__ __launch_bounds__(256, 2)
void k_mma(const __nv_bfloat16* __restrict__ Ah, const __nv_bfloat16* __restrict__ Al,
           const __nv_bfloat16* __restrict__ Bh, const __nv_bfloat16* __restrict__ Bl,
           float* __restrict__ C, float* __restrict__ partial, int M, int N, int K) {
    __shared__ __align__(16) uint16_t sA[2][128 * A_STRIDE];
    __shared__ __align__(16) uint16_t sB[2][KC * B_STRIDE];
    __shared__ float sS[8][32], sS2[8][32];
    int tid = threadIdx.x, wid = tid >> 5, lane = tid & 31;
    int bm = blockIdx.x * 128, bn = blockIdx.y * 128;
    int wm = (wid & 1) * 64, wn = (wid >> 1) * 32;
    int mat = lane >> 3, r = lane & 7;
    int kpt = K >> 5;
    int nst = 3 * kpt;

    float acc[4][4][4];
    #pragma unroll
    for (int i = 0; i < 4; i++)
        #pragma unroll
        for (int j = 0; j < 4; j++)
            #pragma unroll
            for (int v = 0; v < 4; v++) acc[i][j][v] = 0.f;

    uint32_t aBase[2] = { smem_u32(sA[0]), smem_u32(sA[1]) };
    uint32_t bBase[2] = { smem_u32(sB[0]), smem_u32(sB[1]) };

    auto issueA = [&](const __nv_bfloat16* Ap, int koff, int slot) {
        #pragma unroll
        for (int i = 0; i < 2; i++) {
            int seg = i * 256 + tid;
            int row = seg >> 2, cs = (seg & 3) << 3;
            cpa16(aBase[slot] + (row * A_STRIDE + cs) * 2,
                  Ap + (size_t)(bm + row) * K + koff + cs, (bm + row) < M);
        }
    };
    auto issueB = [&](const __nv_bfloat16* Bp, int koff, int slot) {
        #pragma unroll
        for (int i = 0; i < 2; i++) {
            int seg = i * 256 + tid;
            int row = seg >> 4, cs = (seg & 15) << 3;
            cpa16(bBase[slot] + (row * B_STRIDE + cs) * 2,
                  Bp + (size_t)(koff + row) * N + bn + cs, 1);
        }
    };

    issueA(Ah, 0, 0);
    issueB(Bh, 0, 0);
    asm volatile("cp.async.commit_group;" ::: "memory");

    for (int s = 0; s < nst; s++) {
        int k = s / 3, t = s - 3 * k;
        if (s + 1 < nst) {
            int s1 = s + 1, k1 = s1 / 3, t1 = s1 - 3 * k1;
            if (t1 == 0) {
                issueA(Ah, k1 << 5, 0);
                issueB(Bh, k1 << 5, k1 & 1);
            } else if (t1 == 1) {
                issueB(Bl, k1 << 5, (k1 & 1) ^ 1);
            } else {
                issueA(Al, k1 << 5, 1);
            }
            asm volatile("cp.async.commit_group;" ::: "memory");
            asm volatile("cp.async.wait_group 1;" ::: "memory");
        } else {
            asm volatile("cp.async.wait_group 0;" ::: "memory");
        }
        __syncthreads();
        int as = (t == 2) ? 1 : 0;
        int bs = (t == 1) ? ((k & 1) ^ 1) : (k & 1);
        #pragma unroll
        for (int ks = 0; ks < KC / 16; ks++) {
            uint32_t a[4][4], b[4][2];
            #pragma unroll
            for (int mt = 0; mt < 4; mt++) {
                int mrow = wm + mt * 16 + (mat & 1) * 8 + r;
                int kcol = ks * 16 + (mat >> 1) * 8;
                ldsm_x4(a[mt][0], a[mt][1], a[mt][2], a[mt][3],
                        aBase[as] + (mrow * A_STRIDE + kcol) * 2);
            }
            #pragma unroll
            for (int nt = 0; nt < 2; nt++) {
                int krow = ks * 16 + (mat & 1) * 8 + r;
                int ncol = wn + nt * 16 + (mat >> 1) * 8;
                ldsm_x4_t(b[nt * 2][0], b[nt * 2][1], b[nt * 2 + 1][0], b[nt * 2 + 1][1],
                          bBase[bs] + (krow * B_STRIDE + ncol) * 2);
            }
            #pragma unroll
            for (int mt = 0; mt < 4; mt++)
                #pragma unroll
                for (int nt = 0; nt < 4; nt++)
                    mma_bf16(acc[mt][nt], a[mt], b[nt]);
        }
        __syncthreads();
    }

    int g = lane >> 2, tg = lane & 3;
    #pragma unroll
    for (int mt = 0; mt < 4; mt++) {
        #pragma unroll
        for (int nt = 0; nt < 4; nt++) {
            int row0 = bm + wm + mt * 16 + g;
            int col = bn + wn + nt * 8 + tg * 2;
            if (row0 < M) {
                C[(size_t)row0 * N + col] = acc[mt][nt][0];
                C[(size_t)row0 * N + col + 1] = acc[mt][nt][1];
            }
            int row1 = row0 + 8;
            if (row1 < M) {
                C[(size_t)row1 * N + col] = acc[mt][nt][2];
                C[(size_t)row1 * N + col + 1] = acc[mt][nt][3];
            }
        }
    }

    // fused column stats (rows >= M contributed exact zeros)
    #pragma unroll
    for (int nt = 0; nt < 4; nt++) {
        #pragma unroll
        for (int p = 0; p < 2; p++) {
            float ss = 0.f, qq = 0.f;
            #pragma unroll
            for (int mt = 0; mt < 4; mt++) {
                float a0 = acc[mt][nt][p], a1 = acc[mt][nt][p + 2];
                ss += a0 + a1;
                qq += a0 * a0 + a1 * a1;
            }
            #pragma unroll
            for (int off = 16; off >= 4; off >>= 1) {
                ss += __shfl_down_sync(0xffffffff, ss, off);
                qq += __shfl_down_sync(0xffffffff, qq, off);
            }
            if (g == 0) {
                sS[wid][nt * 8 + tg * 2 + p] = ss;
                sS2[wid][nt * 8 + tg * 2 + p] = qq;
            }
        }
    }
    __syncthreads();
    if (tid < 128) {
        int w0 = (tid >> 5) * 2, lc = tid & 31;
        partial[blockIdx.x * 1024 + bn + tid] = sS[w0][lc] + sS[w0 + 1][lc];
        partial[blockIdx.x * 1024 + 512 + bn + tid] = sS2[w0][lc] + sS2[w0 + 1][lc];
    }
}

// ---------------- edge weights + degree histogram ----------------
__global__ void k_edge(const float4* __restrict__ ref_bxyz,
                       const float4* __restrict__ query_bxyz,
                       const int* __restrict__ e_ref,
                       const int* __restrict__ e_query) {
    int e = blockIdx.x * blockDim.x + threadIdx.x;
    if (e >= NEDGE) return;
    int r = e_ref[e], q = e_query[e];
    float4 rb = ref_bxyz[r];
    float4 qb = query_bxyz[q];
    float dx = rb.y - qb.y, dy = rb.z - qb.z, dz = rb.w - qb.w;
    float dist = sqrtf(dx * dx + dy * dy + dz * dz);
    float w = 1.0f / (dist + 1e-8f);
    d_w[e] = w;
    atomicAdd(&d_wsum[q], w);
    atomicAdd(&d_deg[q], 1);
}

// ---------------- single-pass scan ----------------
__global__ void k_scan() {
    __shared__ int wsum[32];
    const int CH = 25;
    int tid = threadIdx.x, lane = tid & 31, wid = tid >> 5;
    int base = tid * CH;
    int s = 0;
    #pragma unroll
    for (int i = 0; i < CH; i++) {
        int idx = base + i;
        if (idx < N_QP) s += d_deg[idx];
    }
    int v = s;
    #pragma unroll
    for (int off = 1; off < 32; off <<= 1) {
        int t = __shfl_up_sync(0xffffffff, v, off);
        if (lane >= off) v += t;
    }
    if (lane == 31) wsum[wid] = v;
    __syncthreads();
    if (wid == 0) {
        int w = wsum[lane];
        #pragma unroll
        for (int off = 1; off < 32; off <<= 1) {
            int t = __shfl_up_sync(0xffffffff, w, off);
            if (lane >= off) w += t;
        }
        wsum[lane] = w;
    }
    __syncthreads();
    int warp_excl = (wid == 0) ? 0 : wsum[wid - 1];
    int run = warp_excl + v - s;
    #pragma unroll
    for (int i = 0; i < CH; i++) {
        int idx = base + i;
        if (idx < N_QP) { d_rowstart[idx] = run; run += d_deg[idx]; }
    }
    if (base < N_QP && base + CH >= N_QP) d_rowstart[N_QP] = run;
}

// ---------------- bucket-fill ----------------
__global__ void k_fill(const int* __restrict__ e_query, const int* __restrict__ e_ref) {
    int e = blockIdx.x * blockDim.x + threadIdx.x;
    if (e >= NEDGE) return;
    int q = e_query[e];
    int pos = atomicAdd(&d_cursor[q], 1) + d_rowstart[q];
    d_rsorted[pos] = e_ref[e];
    d_wsorted[pos] = d_w[e];
}

// ---------------- BN finalize (parallel, 1024 threads) ----------------
__global__ void k_bnfinal(int C, int M, int NBLK, const float* __restrict__ partial,
                          const float* __restrict__ g, const float* __restrict__ b,
                          float* __restrict__ bna, float* __restrict__ bnc) {
    __shared__ float redS[4][256], redQ[4][256];
    int t = threadIdx.x;
    int c = t & 255, chunk = t >> 8;
    float s = 0.f, s2 = 0.f;
    for (int bx = chunk; bx < NBLK; bx += 4) {
        s += partial[bx * 1024 + c];
        s2 += partial[bx * 1024 + 512 + c];
    }
    redS[chunk][c] = s;
    redQ[chunk][c] = s2;
    __syncthreads();
    if (t < C) {
        float S = redS[0][t] + redS[1][t] + redS[2][t] + redS[3][t];
        float Q = redQ[0][t] + redQ[1][t] + redQ[2][t] + redQ[3][t];
        float m = S / (float)M;
        float v = Q / (float)M - m * m;
        float a = g[t] * rsqrtf(v + BN_EPS);
        bna[t] = a;
        bnc[t] = b[t] - a * m;
    }
}

// ---------------- fused gather + x0 ----------------
__global__ void k_gather_x0(const float* __restrict__ bna0, const float* __restrict__ bnc0,
                            const float* __restrict__ bna1, const float* __restrict__ bnc1) {
    __shared__ float sPart[4][128];
    int q = blockIdx.x;
    int tid = threadIdx.x, wid = tid >> 5, lane = tid & 31;
    int s = d_rowstart[q], t = d_rowstart[q + 1];
    float4 acc = make_float4(0.f, 0.f, 0.f, 0.f);
    for (int i = s + wid; i < t; i += 4) {
        int r = d_rsorted[i];
        float w = d_wsorted[i];
        float4 y = *(const float4*)(d_Y1 + (size_t)r * C0 + lane * 4);
        acc.x = fmaf(w, y.x, acc.x); acc.y = fmaf(w, y.y, acc.y);
        acc.z = fmaf(w, y.z, acc.z); acc.w = fmaf(w, y.w, acc.w);
    }
    sPart[wid][lane * 4 + 0] = acc.x;
    sPart[wid][lane * 4 + 1] = acc.y;
    sPart[wid][lane * 4 + 2] = acc.z;
    sPart[wid][lane * 4 + 3] = acc.w;
    __syncthreads();
    int c = tid;
    float sum = sPart[0][c] + sPart[1][c] + sPart[2][c] + sPart[3][c];
    float qf = 0.f;
    if (t > s) qf = bna0[c] * sum * (1.0f / d_wsum[q]) + bnc0[c];
    float sv = d_S[(size_t)q * C0 + c];
    float v = fmaxf(qf + bna1[c] * sv + bnc1[c], 0.f);
    uint16_t h, l;
    split2(v, h, l);
    ((uint16_t*)d_X0H)[(size_t)q * C0 + c] = h;
    ((uint16_t*)d_X0L)[(size_t)q * C0 + c] = l;
}

// ---------------- x1 = relu(a*Y + c), emit split bf16 (C=256) ----------------
__global__ void k_bnrelu_split(const float* __restrict__ Y, int n4,
                               const float* __restrict__ bna, const float* __restrict__ bnc) {
    int qd = blockIdx.x * blockDim.x + threadIdx.x;
    if (qd >= n4) return;
    int i = qd * 4;
    int c = i & 255;
    float4 y = *(float4*)(Y + i);
    float v0 = fmaxf(bna[c] * y.x + bnc[c], 0.f);
    float v1 = fmaxf(bna[c + 1] * y.y + bnc[c + 1], 0.f);
    float v2 = fmaxf(bna[c + 2] * y.z + bnc[c + 2], 0.f);
    float v3 = fmaxf(bna[c + 3] * y.w + bnc[c + 3], 0.f);
    uint16_t h[4], l[4];
    split2(v0, h[0], l[0]); split2(v1, h[1], l[1]);
    split2(v2, h[2], l[2]); split2(v3, h[3], l[3]);
    *(uint2*)((uint16_t*)d_X1H + i) = make_uint2(h[0] | ((uint32_t)h[1] << 16), h[2] | ((uint32_t)h[3] << 16));
    *(uint2*)((uint16_t*)d_X1L + i) = make_uint2(l[0] | ((uint32_t)l[1] << 16), l[2] | ((uint32_t)l[3] << 16));
}

// ---------------- out = relu(a*Y + c) fp32 (C=256) ----------------
__global__ void k_bnrelu_out(const float* __restrict__ Y, float* __restrict__ X, int n4,
                             const float* __restrict__ bna, const float* __restrict__ bnc) {
    int qd = blockIdx.x * blockDim.x + threadIdx.x;
    if (qd >= n4) return;
    int i = qd * 4;
    int c = i & 255;
    float4 y = *(float4*)(Y + i);
    float4 o;
    o.x = fmaxf(bna[c] * y.x + bnc[c], 0.f);
    o.y = fmaxf(bna[c + 1] * y.y + bnc[c + 1], 0.f);
    o.z = fmaxf(bna[c + 2] * y.z + bnc[c + 2], 0.f);
    o.w = fmaxf(bna[c + 3] * y.w + bnc[c + 3], 0.f);
    *(float4*)(X + i) = o;
}

// ---------------- launcher ----------------
extern "C" void kernel_launch(void* const* d_in, const int* in_sizes, int n_in,
                              void* d_out, int out_size) {
    const float* ref_bxyz   = (const float*)d_in[0];
    const float* ref_feat   = (const float*)d_in[1];
    const float* query_bxyz = (const float*)d_in[2];
    const float* query_feat = (const float*)d_in[3];
    const int*   e_ref      = (const int*)d_in[4];
    const int*   e_query    = (const int*)d_in[5];
    const float* Wf0   = (const float*)d_in[6];
    const float* gf0   = (const float*)d_in[7];
    const float* bf0   = (const float*)d_in[8];
    const float* Ws0   = (const float*)d_in[9];
    const float* gs0   = (const float*)d_in[10];
    const float* bs0   = (const float*)d_in[11];
    const float* W1    = (const float*)d_in[12];
    const float* g1    = (const float*)d_in[14];
    const float* beta1 = (const float*)d_in[15];
    const float* W2    = (const float*)d_in[16];
    const float* g2    = (const float*)d_in[18];
    const float* beta2 = (const float*)d_in[19];
    float* out = (float*)d_out;

    float *pY1, *pS, *pY2, *pY3, *pPart, *pBN;
    cudaGetSymbolAddress((void**)&pY1, d_Y1);
    cudaGetSymbolAddress((void**)&pS,  d_S);
    cudaGetSymbolAddress((void**)&pY2, d_Y2);
    cudaGetSymbolAddress((void**)&pY3, d_Y3);
    cudaGetSymbolAddress((void**)&pPart, d_partial);
    cudaGetSymbolAddress((void**)&pBN, d_bn);
    float* pPartA = pPart;
    float* pPartB = pPart + 400 * 1024;
    float* bna0 = pBN;            float* bnc0 = pBN + 256;
    float* bna1 = pBN + 512;      float* bnc1 = pBN + 768;
    float* bna2 = pBN + 1024;     float* bnc2 = pBN + 1280;
    float* bna3 = pBN + 1536;     float* bnc3 = pBN + 1792;

    __nv_bfloat16 *pRefH, *pRefL, *pQH, *pQL, *pX0H, *pX0L, *pX1H, *pX1L;
    __nv_bfloat16 *pWf0H, *pWf0L, *pWs0H, *pWs0L, *pW1H, *pW1L, *pW2H, *pW2L;
    cudaGetSymbolAddress((void**)&pRefH, d_refH); cudaGetSymbolAddress((void**)&pRefL, d_refL);
    cudaGetSymbolAddress((void**)&pQH, d_qH);     cudaGetSymbolAddress((void**)&pQL, d_qL);
    cudaGetSymbolAddress((void**)&pX0H, d_X0H);   cudaGetSymbolAddress((void**)&pX0L, d_X0L);
    cudaGetSymbolAddress((void**)&pX1H, d_X1H);   cudaGetSymbolAddress((void**)&pX1L, d_X1L);
    cudaGetSymbolAddress((void**)&pWf0H, d_Wf0H); cudaGetSymbolAddress((void**)&pWf0L, d_Wf0L);
    cudaGetSymbolAddress((void**)&pWs0H, d_Ws0H); cudaGetSymbolAddress((void**)&pWs0L, d_Ws0L);
    cudaGetSymbolAddress((void**)&pW1H, d_W1H);   cudaGetSymbolAddress((void**)&pW1L, d_W1L);
    cudaGetSymbolAddress((void**)&pW2H, d_W2H);   cudaGetSymbolAddress((void**)&pW2L, d_W2L);

    static cudaStream_t s1 = nullptr, s2 = nullptr, s3 = nullptr;
    static cudaEvent_t evStart, evEdge, evS, evA1;
    if (!s1) {
        cudaStreamCreateWithFlags(&s1, cudaStreamNonBlocking);
        cudaStreamCreateWithFlags(&s2, cudaStreamNonBlocking);
        cudaStreamCreateWithFlags(&s3, cudaStreamNonBlocking);
        cudaEventCreateWithFlags(&evStart, cudaEventDisableTiming);
        cudaEventCreateWithFlags(&evEdge, cudaEventDisableTiming);
        cudaEventCreateWithFlags(&evS, cudaEventDisableTiming);
        cudaEventCreateWithFlags(&evA1, cudaEventDisableTiming);
    }

    cudaEventRecord(evStart, 0);

    // s1: edge preprocessing (fully independent)
    cudaStreamWaitEvent(s1, evStart, 0);
    k_init<<<(N_QP / 4 + 256) / 256, 256, 0, s1>>>();
    k_edge<<<(NEDGE + 255) / 256, 256, 0, s1>>>((const float4*)ref_bxyz,
                                                (const float4*)query_bxyz, e_ref, e_query);
    k_scan<<<1, 1024, 0, s1>>>();
    k_fill<<<(NEDGE + 255) / 256, 256, 0, s1>>>(e_query, e_ref);
    cudaEventRecord(evEdge, s1);

    // s2: other splits + skip-branch GEMM + its BN finalize
    cudaStreamWaitEvent(s2, evStart, 0);
    k_split_b<<<(QB_TOT + 255) / 256, 256, 0, s2>>>(query_feat, Ws0, W1, W2);
    {
        dim3 g((N_QP + 127) / 128, 1);
        k_mma<<<g, 256, 0, s2>>>(pQH, pQL, pWs0H, pWs0L, pS, pPartB, N_QP, C0, C0);
        k_bnfinal<<<1, 1024, 0, s2>>>(C0, N_QP, g.x, pPartB, gs0, bs0, bna1, bnc1);
    }
    cudaEventRecord(evS, s2);

    // s3: second-half A split (overlaps first-half GEMM on main stream)
    cudaStreamWaitEvent(s3, evStart, 0);
    k_split_a1<<<(QR1 + 255) / 256, 256, 0, s3>>>(ref_feat);
    cudaEventRecord(evA1, s3);

    // main chain: first-half split -> GEMM-A, then GEMM-B after evA1
    k_split_a0<<<(QA0_TOT + 255) / 256, 256>>>(ref_feat, Wf0);
    {
        dim3 gA(MHALF / 128, 1);     // 200 CTAs: rows [0, MHALF)
        k_mma<<<gA, 256>>>(pRefH, pRefL, pWf0H, pWf0L, pY1, pPartA, MHALF, C0, C0);
    }
    cudaStreamWaitEvent(0, evA1, 0);
    {
        dim3 gB((MREST + 127) / 128, 1);   // 191 CTAs: rows [MHALF, N_REFP)
        k_mma<<<gB, 256>>>(pRefH + (size_t)MHALF * C0, pRefL + (size_t)MHALF * C0,
                           pWf0H, pWf0L, pY1 + (size_t)MHALF * C0,
                           pPartA + 200 * 1024, MREST, C0, C0);
        k_bnfinal<<<1, 1024>>>(C0, N_REFP, 200 + gB.x, pPartA, gf0, bf0, bna0, bnc0);
    }
    cudaStreamWaitEvent(0, evEdge, 0);
    cudaStreamWaitEvent(0, evS, 0);
    k_gather_x0<<<N_QP, 128>>>(bna0, bnc0, bna1, bnc1);

    {
        dim3 g((N_QP + 127) / 128, 2);
        k_mma<<<g, 256>>>(pX0H, pX0L, pW1H, pW1L, pY2, pPartA, N_QP, C1, C0);
        k_bnfinal<<<1, 1024>>>(C1, N_QP, g.x, pPartA, g1, beta1, bna2, bnc2);
    }
    k_bnrelu_split<<<(N_QP * C1 / 4 + 255) / 256, 256>>>(pY2, N_QP * C1 / 4, bna2, bnc2);

    {
        dim3 g((N_QP + 127) / 128, 2);
        k_mma<<<g, 256>>>(pX1H, pX1L, pW2H, pW2L, pY3, pPartA, N_QP, C1, C1);
        k_bnfinal<<<1, 1024>>>(C1, N_QP, g.x, pPartA, g2, beta2, bna3, bnc3);
    }
    k_bnrelu_out<<<(N_QP * C1 / 4 + 255) / 256, 256>>>(pY3, out, N_QP * C1 / 4, bna3, bnc3);
}

// round 16
// speedup vs baseline: 1.0401x; 1.0329x over previous
#include <cuda_runtime.h>
#include <cuda_bf16.h>
#include <math.h>
#include <cstdint>

#define N_QP   25000
#define N_REFP 50000
#define NEDGE  400000
#define C0     128
#define C1     256
#define BN_EPS 1e-5f

// ---------------- scratch ----------------
__device__ float d_w[NEDGE];
__device__ float d_wsum[N_QP];
__device__ int   d_deg[N_QP];
__device__ int   d_cursor[N_QP];
__device__ int   d_rowstart[N_QP + 1];
__device__ int   d_rsorted[NEDGE];
__device__ float d_wsorted[NEDGE];
__device__ float d_Y1[(size_t)N_REFP * C0];
__device__ float d_S [(size_t)N_QP * C0];
__device__ float d_Y2[(size_t)N_QP * C1];
__device__ float d_Y3[(size_t)N_QP * C1];
__device__ float d_partial[600 * 1024];      // region A @0, region B @400*1024
__device__ float d_bn[4][2][256];
__device__ __nv_bfloat16 d_refH[(size_t)N_REFP * C0], d_refL[(size_t)N_REFP * C0];
__device__ __nv_bfloat16 d_qH[(size_t)N_QP * C0],     d_qL[(size_t)N_QP * C0];
__device__ __nv_bfloat16 d_X0H[(size_t)N_QP * C0],    d_X0L[(size_t)N_QP * C0];
__device__ __nv_bfloat16 d_X1H[(size_t)N_QP * C1],    d_X1L[(size_t)N_QP * C1];
__device__ __nv_bfloat16 d_Wf0H[C0 * C0], d_Wf0L[C0 * C0];
__device__ __nv_bfloat16 d_Ws0H[C0 * C0], d_Ws0L[C0 * C0];
__device__ __nv_bfloat16 d_W1H[C0 * C1],  d_W1L[C0 * C1];
__device__ __nv_bfloat16 d_W2H[C1 * C1],  d_W2L[C1 * C1];

// ======================= helpers =======================
__device__ __forceinline__ uint32_t smem_u32(const void* p) {
    uint32_t a;
    asm("{ .reg .u64 t; cvta.to.shared.u64 t, %1; cvt.u32.u64 %0, t; }" : "=r"(a) : "l"(p));
    return a;
}
__device__ __forceinline__ void ldsm_x4(uint32_t& r0, uint32_t& r1, uint32_t& r2, uint32_t& r3,
                                        uint32_t addr) {
    asm volatile("ldmatrix.sync.aligned.m8n8.x4.shared.b16 {%0,%1,%2,%3}, [%4];"
                 : "=r"(r0), "=r"(r1), "=r"(r2), "=r"(r3) : "r"(addr));
}
__device__ __forceinline__ void ldsm_x4_t(uint32_t& r0, uint32_t& r1, uint32_t& r2, uint32_t& r3,
                                          uint32_t addr) {
    asm volatile("ldmatrix.sync.aligned.m8n8.x4.trans.shared.b16 {%0,%1,%2,%3}, [%4];"
                 : "=r"(r0), "=r"(r1), "=r"(r2), "=r"(r3) : "r"(addr));
}
__device__ __forceinline__ void mma_bf16(float* c, const uint32_t* a, const uint32_t* b) {
    asm volatile(
        "mma.sync.aligned.m16n8k16.row.col.f32.bf16.bf16.f32 "
        "{%0,%1,%2,%3}, {%4,%5,%6,%7}, {%8,%9}, {%0,%1,%2,%3};"
        : "+f"(c[0]), "+f"(c[1]), "+f"(c[2]), "+f"(c[3])
        : "r"(a[0]), "r"(a[1]), "r"(a[2]), "r"(a[3]), "r"(b[0]), "r"(b[1]));
}
__device__ __forceinline__ void cpa16(uint32_t dst, const void* src, int valid) {
    asm volatile("cp.async.cg.shared.global [%0], [%1], 16, %2;"
                 :: "r"(dst), "l"(src), "r"(valid ? 16 : 0) : "memory");
}
__device__ __forceinline__ void split2(float v, uint16_t& h, uint16_t& l) {
    __nv_bfloat16 bh = __float2bfloat16(v);
    __nv_bfloat16 bl = __float2bfloat16(v - __bfloat162float(bh));
    h = *(uint16_t*)&bh; l = *(uint16_t*)&bl;
}
__device__ __forceinline__ void split4_store(const float* X, uint16_t* H, uint16_t* L, int q) {
    float4 v = *(const float4*)(X + (size_t)q * 4);
    uint16_t h[4], l[4];
    split2(v.x, h[0], l[0]); split2(v.y, h[1], l[1]);
    split2(v.z, h[2], l[2]); split2(v.w, h[3], l[3]);
    *(uint2*)(H + (size_t)q * 4) = make_uint2(h[0] | ((uint32_t)h[1] << 16), h[2] | ((uint32_t)h[3] << 16));
    *(uint2*)(L + (size_t)q * 4) = make_uint2(l[0] | ((uint32_t)l[1] << 16), l[2] | ((uint32_t)l[3] << 16));
}

// ---------------- split kernels (R12 layout) ----------------
#define QR  1600000
#define QQ  800000
#define QW0 4096
#define QW1 4096
#define QW2 8192
#define QW3 16384
#define QA_TOT (QR + QW0)
#define QB_TOT (QQ + QW1 + QW2 + QW3)
__global__ void k_split_a(const float* __restrict__ ref, const float* __restrict__ Wf0) {
    int i = blockIdx.x * blockDim.x + threadIdx.x;
    if (i >= QA_TOT) return;
    if (i < QR) { split4_store(ref, (uint16_t*)d_refH, (uint16_t*)d_refL, i); return; }
    i -= QR;
    split4_store(Wf0, (uint16_t*)d_Wf0H, (uint16_t*)d_Wf0L, i);
}
__global__ void k_split_b(const float* __restrict__ qf, const float* __restrict__ Ws0,
                          const float* __restrict__ W1, const float* __restrict__ W2) {
    int i = blockIdx.x * blockDim.x + threadIdx.x;
    if (i >= QB_TOT) return;
    if (i < QQ) { split4_store(qf, (uint16_t*)d_qH, (uint16_t*)d_qL, i); return; }
    i -= QQ;
    if (i < QW1) { split4_store(Ws0, (uint16_t*)d_Ws0H, (uint16_t*)d_Ws0L, i); return; }
    i -= QW1;
    if (i < QW2) { split4_store(W1, (uint16_t*)d_W1H, (uint16_t*)d_W1L, i); return; }
    i -= QW2;
    split4_store(W2, (uint16_t*)d_W2H, (uint16_t*)d_W2L, i);
}

// ---------------- init ----------------
__global__ void k_init() {
    int i = blockIdx.x * blockDim.x + threadIdx.x;
    if (i >= N_QP / 4 + 1) return;
    if (i * 4 + 3 < N_QP) {
        *(float4*)(d_wsum + i * 4) = make_float4(0.f, 0.f, 0.f, 0.f);
        *(int4*)(d_deg + i * 4) = make_int4(0, 0, 0, 0);
        *(int4*)(d_cursor + i * 4) = make_int4(0, 0, 0, 0);
    } else {
        for (int j = i * 4; j < N_QP; j++) { d_wsum[j] = 0.f; d_deg[j] = 0; d_cursor[j] = 0; }
    }
}

// ---------------- pipelined split-bf16 GEMM with fused column stats (R12-proven) ----------------
#define KC 32
#define A_STRIDE 40
#define B_STRIDE 136
__global__ __launch_bounds__(256, 2)
void k_mma(const __nv_bfloat16* __restrict__ Ah, const __nv_bfloat16* __restrict__ Al,
           const __nv_bfloat16* __restrict__ Bh, const __nv_bfloat16* __restrict__ Bl,
           float* __restrict__ C, float* __restrict__ partial, int M, int N, int K) {
    __shared__ __align__(16) uint16_t sA[2][128 * A_STRIDE];
    __shared__ __align__(16) uint16_t sB[2][KC * B_STRIDE];
    __shared__ float sS[8][32], sS2[8][32];
    int tid = threadIdx.x, wid = tid >> 5, lane = tid & 31;
    int bm = blockIdx.x * 128, bn = blockIdx.y * 128;
    int wm = (wid & 1) * 64, wn = (wid >> 1) * 32;
    int mat = lane >> 3, r = lane & 7;
    int kpt = K >> 5;
    int nst = 3 * kpt;

    float acc[4][4][4];
    #pragma unroll
    for (int i = 0; i < 4; i++)
        #pragma unroll
        for (int j = 0; j < 4; j++)
            #pragma unroll
            for (int v = 0; v < 4; v++) acc[i][j][v] = 0.f;

    uint32_t aBase[2] = { smem_u32(sA[0]), smem_u32(sA[1]) };
    uint32_t bBase[2] = { smem_u32(sB[0]), smem_u32(sB[1]) };

    auto issueA = [&](const __nv_bfloat16* Ap, int koff, int slot) {
        #pragma unroll
        for (int i = 0; i < 2; i++) {
            int seg = i * 256 + tid;
            int row = seg >> 2, cs = (seg & 3) << 3;
            cpa16(aBase[slot] + (row * A_STRIDE + cs) * 2,
                  Ap + (size_t)(bm + row) * K + koff + cs, (bm + row) < M);
        }
    };
    auto issueB = [&](const __nv_bfloat16* Bp, int koff, int slot) {
        #pragma unroll
        for (int i = 0; i < 2; i++) {
            int seg = i * 256 + tid;
            int row = seg >> 4, cs = (seg & 15) << 3;
            cpa16(bBase[slot] + (row * B_STRIDE + cs) * 2,
                  Bp + (size_t)(koff + row) * N + bn + cs, 1);
        }
    };

    issueA(Ah, 0, 0);
    issueB(Bh, 0, 0);
    asm volatile("cp.async.commit_group;" ::: "memory");

    for (int s = 0; s < nst; s++) {
        int k = s / 3, t = s - 3 * k;
        if (s + 1 < nst) {
            int s1 = s + 1, k1 = s1 / 3, t1 = s1 - 3 * k1;
            if (t1 == 0) {
                issueA(Ah, k1 << 5, 0);
                issueB(Bh, k1 << 5, k1 & 1);
            } else if (t1 == 1) {
                issueB(Bl, k1 << 5, (k1 & 1) ^ 1);
            } else {
                issueA(Al, k1 << 5, 1);
            }
            asm volatile("cp.async.commit_group;" ::: "memory");
            asm volatile("cp.async.wait_group 1;" ::: "memory");
        } else {
            asm volatile("cp.async.wait_group 0;" ::: "memory");
        }
        __syncthreads();
        int as = (t == 2) ? 1 : 0;
        int bs = (t == 1) ? ((k & 1) ^ 1) : (k & 1);
        #pragma unroll
        for (int ks = 0; ks < KC / 16; ks++) {
            uint32_t a[4][4], b[4][2];
            #pragma unroll
            for (int mt = 0; mt < 4; mt++) {
                int mrow = wm + mt * 16 + (mat & 1) * 8 + r;
                int kcol = ks * 16 + (mat >> 1) * 8;
                ldsm_x4(a[mt][0], a[mt][1], a[mt][2], a[mt][3],
                        aBase[as] + (mrow * A_STRIDE + kcol) * 2);
            }
            #pragma unroll
            for (int nt = 0; nt < 2; nt++) {
                int krow = ks * 16 + (mat & 1) * 8 + r;
                int ncol = wn + nt * 16 + (mat >> 1) * 8;
                ldsm_x4_t(b[nt * 2][0], b[nt * 2][1], b[nt * 2 + 1][0], b[nt * 2 + 1][1],
                          bBase[bs] + (krow * B_STRIDE + ncol) * 2);
            }
            #pragma unroll
            for (int mt = 0; mt < 4; mt++)
                #pragma unroll
                for (int nt = 0; nt < 4; nt++)
                    mma_bf16(acc[mt][nt], a[mt], b[nt]);
        }
        __syncthreads();
    }

    int g = lane >> 2, tg = lane & 3;
    #pragma unroll
    for (int mt = 0; mt < 4; mt++) {
        #pragma unroll
        for (int nt = 0; nt < 4; nt++) {
            int row0 = bm + wm + mt * 16 + g;
            int col = bn + wn + nt * 8 + tg * 2;
            if (row0 < M) {
                C[(size_t)row0 * N + col] = acc[mt][nt][0];
                C[(size_t)row0 * N + col + 1] = acc[mt][nt][1];
            }
            int row1 = row0 + 8;
            if (row1 < M) {
                C[(size_t)row1 * N + col] = acc[mt][nt][2];
                C[(size_t)row1 * N + col + 1] = acc[mt][nt][3];
            }
        }
    }

    // fused column stats (rows >= M contributed exact zeros)
    #pragma unroll
    for (int nt = 0; nt < 4; nt++) {
        #pragma unroll
        for (int p = 0; p < 2; p++) {
            float ss = 0.f, qq = 0.f;
            #pragma unroll
            for (int mt = 0; mt < 4; mt++) {
                float a0 = acc[mt][nt][p], a1 = acc[mt][nt][p + 2];
                ss += a0 + a1;
                qq += a0 * a0 + a1 * a1;
            }
            #pragma unroll
            for (int off = 16; off >= 4; off >>= 1) {
                ss += __shfl_down_sync(0xffffffff, ss, off);
                qq += __shfl_down_sync(0xffffffff, qq, off);
            }
            if (g == 0) {
                sS[wid][nt * 8 + tg * 2 + p] = ss;
                sS2[wid][nt * 8 + tg * 2 + p] = qq;
            }
        }
    }
    __syncthreads();
    if (tid < 128) {
        int w0 = (tid >> 5) * 2, lc = tid & 31;
        partial[blockIdx.x * 1024 + bn + tid] = sS[w0][lc] + sS[w0 + 1][lc];
        partial[blockIdx.x * 1024 + 512 + bn + tid] = sS2[w0][lc] + sS2[w0 + 1][lc];
    }
}

// ---------------- edge weights + degree histogram ----------------
__global__ void k_edge(const float4* __restrict__ ref_bxyz,
                       const float4* __restrict__ query_bxyz,
                       const int* __restrict__ e_ref,
                       const int* __restrict__ e_query) {
    int e = blockIdx.x * blockDim.x + threadIdx.x;
    if (e >= NEDGE) return;
    int r = e_ref[e], q = e_query[e];
    float4 rb = ref_bxyz[r];
    float4 qb = query_bxyz[q];
    float dx = rb.y - qb.y, dy = rb.z - qb.z, dz = rb.w - qb.w;
    float dist = sqrtf(dx * dx + dy * dy + dz * dz);
    float w = 1.0f / (dist + 1e-8f);
    d_w[e] = w;
    atomicAdd(&d_wsum[q], w);
    atomicAdd(&d_deg[q], 1);
}

// ---------------- single-pass scan ----------------
__global__ void k_scan() {
    __shared__ int wsum[32];
    const int CH = 25;
    int tid = threadIdx.x, lane = tid & 31, wid = tid >> 5;
    int base = tid * CH;
    int s = 0;
    #pragma unroll
    for (int i = 0; i < CH; i++) {
        int idx = base + i;
        if (idx < N_QP) s += d_deg[idx];
    }
    int v = s;
    #pragma unroll
    for (int off = 1; off < 32; off <<= 1) {
        int t = __shfl_up_sync(0xffffffff, v, off);
        if (lane >= off) v += t;
    }
    if (lane == 31) wsum[wid] = v;
    __syncthreads();
    if (wid == 0) {
        int w = wsum[lane];
        #pragma unroll
        for (int off = 1; off < 32; off <<= 1) {
            int t = __shfl_up_sync(0xffffffff, w, off);
            if (lane >= off) w += t;
        }
        wsum[lane] = w;
    }
    __syncthreads();
    int warp_excl = (wid == 0) ? 0 : wsum[wid - 1];
    int run = warp_excl + v - s;
    #pragma unroll
    for (int i = 0; i < CH; i++) {
        int idx = base + i;
        if (idx < N_QP) { d_rowstart[idx] = run; run += d_deg[idx]; }
    }
    if (base < N_QP && base + CH >= N_QP) d_rowstart[N_QP] = run;
}

// ---------------- bucket-fill ----------------
__global__ void k_fill(const int* __restrict__ e_query, const int* __restrict__ e_ref) {
    int e = blockIdx.x * blockDim.x + threadIdx.x;
    if (e >= NEDGE) return;
    int q = e_query[e];
    int pos = atomicAdd(&d_cursor[q], 1) + d_rowstart[q];
    d_rsorted[pos] = e_ref[e];
    d_wsorted[pos] = d_w[e];
}

// ---------------- BN finalize (parallel, 1024 threads) ----------------
__global__ void k_bnfinal(int C, int M, int NBLK, const float* __restrict__ partial,
                          const float* __restrict__ g, const float* __restrict__ b,
                          float* __restrict__ bna, float* __restrict__ bnc) {
    __shared__ float redS[4][256], redQ[4][256];
    int t = threadIdx.x;
    int c = t & 255, chunk = t >> 8;
    float s = 0.f, s2 = 0.f;
    for (int bx = chunk; bx < NBLK; bx += 4) {
        s += partial[bx * 1024 + c];
        s2 += partial[bx * 1024 + 512 + c];
    }
    redS[chunk][c] = s;
    redQ[chunk][c] = s2;
    __syncthreads();
    if (t < C) {
        float S = redS[0][t] + redS[1][t] + redS[2][t] + redS[3][t];
        float Q = redQ[0][t] + redQ[1][t] + redQ[2][t] + redQ[3][t];
        float m = S / (float)M;
        float v = Q / (float)M - m * m;
        float a = g[t] * rsqrtf(v + BN_EPS);
        bna[t] = a;
        bnc[t] = b[t] - a * m;
    }
}

// ---------------- fused gather + x0: 2 queries per 256-thread block ----------------
__global__ void k_gather_x0(const float* __restrict__ bna0, const float* __restrict__ bnc0,
                            const float* __restrict__ bna1, const float* __restrict__ bnc1) {
    __shared__ float sPart[2][4][128];
    int tid = threadIdx.x;
    int sub = tid >> 7;                 // 0 or 1: which query in this block
    int stid = tid & 127;
    int q = blockIdx.x * 2 + sub;
    int wid = stid >> 5, lane = stid & 31;
    int s = d_rowstart[q], t = d_rowstart[q + 1];
    float4 acc = make_float4(0.f, 0.f, 0.f, 0.f);
    for (int i = s + wid; i < t; i += 4) {
        int r = d_rsorted[i];
        float w = d_wsorted[i];
        float4 y = *(const float4*)(d_Y1 + (size_t)r * C0 + lane * 4);
        acc.x = fmaf(w, y.x, acc.x); acc.y = fmaf(w, y.y, acc.y);
        acc.z = fmaf(w, y.z, acc.z); acc.w = fmaf(w, y.w, acc.w);
    }
    sPart[sub][wid][lane * 4 + 0] = acc.x;
    sPart[sub][wid][lane * 4 + 1] = acc.y;
    sPart[sub][wid][lane * 4 + 2] = acc.z;
    sPart[sub][wid][lane * 4 + 3] = acc.w;
    __syncthreads();
    int c = stid;
    float sum = sPart[sub][0][c] + sPart[sub][1][c] + sPart[sub][2][c] + sPart[sub][3][c];
    float qf = 0.f;
    if (t > s) qf = bna0[c] * sum * (1.0f / d_wsum[q]) + bnc0[c];
    float sv = d_S[(size_t)q * C0 + c];
    float v = fmaxf(qf + bna1[c] * sv + bnc1[c], 0.f);
    uint16_t h, l;
    split2(v, h, l);
    ((uint16_t*)d_X0H)[(size_t)q * C0 + c] = h;
    ((uint16_t*)d_X0L)[(size_t)q * C0 + c] = l;
}

// ---------------- x1 = relu(a*Y + c), emit split bf16 (C=256) ----------------
__global__ void k_bnrelu_split(const float* __restrict__ Y, int n4,
                               const float* __restrict__ bna, const float* __restrict__ bnc) {
    int qd = blockIdx.x * blockDim.x + threadIdx.x;
    if (qd >= n4) return;
    int i = qd * 4;
    int c = i & 255;
    float4 y = *(float4*)(Y + i);
    float v0 = fmaxf(bna[c] * y.x + bnc[c], 0.f);
    float v1 = fmaxf(bna[c + 1] * y.y + bnc[c + 1], 0.f);
    float v2 = fmaxf(bna[c + 2] * y.z + bnc[c + 2], 0.f);
    float v3 = fmaxf(bna[c + 3] * y.w + bnc[c + 3], 0.f);
    uint16_t h[4], l[4];
    split2(v0, h[0], l[0]); split2(v1, h[1], l[1]);
    split2(v2, h[2], l[2]); split2(v3, h[3], l[3]);
    *(uint2*)((uint16_t*)d_X1H + i) = make_uint2(h[0] | ((uint32_t)h[1] << 16), h[2] | ((uint32_t)h[3] << 16));
    *(uint2*)((uint16_t*)d_X1L + i) = make_uint2(l[0] | ((uint32_t)l[1] << 16), l[2] | ((uint32_t)l[3] << 16));
}

// ---------------- out = relu(a*Y + c) fp32 (C=256) ----------------
__global__ void k_bnrelu_out(const float* __restrict__ Y, float* __restrict__ X, int n4,
                             const float* __restrict__ bna, const float* __restrict__ bnc) {
    int qd = blockIdx.x * blockDim.x + threadIdx.x;
    if (qd >= n4) return;
    int i = qd * 4;
    int c = i & 255;
    float4 y = *(float4*)(Y + i);
    float4 o;
    o.x = fmaxf(bna[c] * y.x + bnc[c], 0.f);
    o.y = fmaxf(bna[c + 1] * y.y + bnc[c + 1], 0.f);
    o.z = fmaxf(bna[c + 2] * y.z + bnc[c + 2], 0.f);
    o.w = fmaxf(bna[c + 3] * y.w + bnc[c + 3], 0.f);
    *(float4*)(X + i) = o;
}

// ---------------- launcher ----------------
extern "C" void kernel_launch(void* const* d_in, const int* in_sizes, int n_in,
                              void* d_out, int out_size) {
    const float* ref_bxyz   = (const float*)d_in[0];
    const float* ref_feat   = (const float*)d_in[1];
    const float* query_bxyz = (const float*)d_in[2];
    const float* query_feat = (const float*)d_in[3];
    const int*   e_ref      = (const int*)d_in[4];
    const int*   e_query    = (const int*)d_in[5];
    const float* Wf0   = (const float*)d_in[6];
    const float* gf0   = (const float*)d_in[7];
    const float* bf0   = (const float*)d_in[8];
    const float* Ws0   = (const float*)d_in[9];
    const float* gs0   = (const float*)d_in[10];
    const float* bs0   = (const float*)d_in[11];
    const float* W1    = (const float*)d_in[12];
    const float* g1    = (const float*)d_in[14];
    const float* beta1 = (const float*)d_in[15];
    const float* W2    = (const float*)d_in[16];
    const float* g2    = (const float*)d_in[18];
    const float* beta2 = (const float*)d_in[19];
    float* out = (float*)d_out;

    float *pY1, *pS, *pY2, *pY3, *pPart, *pBN;
    cudaGetSymbolAddress((void**)&pY1, d_Y1);
    cudaGetSymbolAddress((void**)&pS,  d_S);
    cudaGetSymbolAddress((void**)&pY2, d_Y2);
    cudaGetSymbolAddress((void**)&pY3, d_Y3);
    cudaGetSymbolAddress((void**)&pPart, d_partial);
    cudaGetSymbolAddress((void**)&pBN, d_bn);
    float* pPartA = pPart;
    float* pPartB = pPart + 400 * 1024;
    float* bna0 = pBN;            float* bnc0 = pBN + 256;
    float* bna1 = pBN + 512;      float* bnc1 = pBN + 768;
    float* bna2 = pBN + 1024;     float* bnc2 = pBN + 1280;
    float* bna3 = pBN + 1536;     float* bnc3 = pBN + 1792;

    __nv_bfloat16 *pRefH, *pRefL, *pQH, *pQL, *pX0H, *pX0L, *pX1H, *pX1L;
    __nv_bfloat16 *pWf0H, *pWf0L, *pWs0H, *pWs0L, *pW1H, *pW1L, *pW2H, *pW2L;
    cudaGetSymbolAddress((void**)&pRefH, d_refH); cudaGetSymbolAddress((void**)&pRefL, d_refL);
    cudaGetSymbolAddress((void**)&pQH, d_qH);     cudaGetSymbolAddress((void**)&pQL, d_qL);
    cudaGetSymbolAddress((void**)&pX0H, d_X0H);   cudaGetSymbolAddress((void**)&pX0L, d_X0L);
    cudaGetSymbolAddress((void**)&pX1H, d_X1H);   cudaGetSymbolAddress((void**)&pX1L, d_X1L);
    cudaGetSymbolAddress((void**)&pWf0H, d_Wf0H); cudaGetSymbolAddress((void**)&pWf0L, d_Wf0L);
    cudaGetSymbolAddress((void**)&pWs0H, d_Ws0H); cudaGetSymbolAddress((void**)&pWs0L, d_Ws0L);
    cudaGetSymbolAddress((void**)&pW1H, d_W1H);   cudaGetSymbolAddress((void**)&pW1L, d_W1L);
    cudaGetSymbolAddress((void**)&pW2H, d_W2H);   cudaGetSymbolAddress((void**)&pW2L, d_W2L);

    static cudaStream_t s1 = nullptr, s2 = nullptr;
    static cudaEvent_t evStart, evEdge, evS;
    if (!s1) {
        cudaStreamCreateWithFlags(&s1, cudaStreamNonBlocking);
        cudaStreamCreateWithFlags(&s2, cudaStreamNonBlocking);
        cudaEventCreateWithFlags(&evStart, cudaEventDisableTiming);
        cudaEventCreateWithFlags(&evEdge, cudaEventDisableTiming);
        cudaEventCreateWithFlags(&evS, cudaEventDisableTiming);
    }

    cudaEventRecord(evStart, 0);

    // s1: edge preprocessing (fully independent)
    cudaStreamWaitEvent(s1, evStart, 0);
    k_init<<<(N_QP / 4 + 256) / 256, 256, 0, s1>>>();
    k_edge<<<(NEDGE + 255) / 256, 256, 0, s1>>>((const float4*)ref_bxyz,
                                                (const float4*)query_bxyz, e_ref, e_query);
    k_scan<<<1, 1024, 0, s1>>>();
    k_fill<<<(NEDGE + 255) / 256, 256, 0, s1>>>(e_query, e_ref);
    cudaEventRecord(evEdge, s1);

    // s2: other splits + skip-branch GEMM + its BN finalize
    cudaStreamWaitEvent(s2, evStart, 0);
    k_split_b<<<(QB_TOT + 255) / 256, 256, 0, s2>>>(query_feat, Ws0, W1, W2);
    {
        dim3 g((N_QP + 127) / 128, 1);
        k_mma<<<g, 256, 0, s2>>>(pQH, pQL, pWs0H, pWs0L, pS, pPartB, N_QP, C0, C0);
        k_bnfinal<<<1, 1024, 0, s2>>>(C0, N_QP, g.x, pPartB, gs0, bs0, bna1, bnc1);
    }
    cudaEventRecord(evS, s2);

    // main chain
    k_split_a<<<(QA_TOT + 255) / 256, 256>>>(ref_feat, Wf0);
    {
        dim3 g((N_REFP + 127) / 128, 1);
        k_mma<<<g, 256>>>(pRefH, pRefL, pWf0H, pWf0L, pY1, pPartA, N_REFP, C0, C0);
        k_bnfinal<<<1, 1024>>>(C0, N_REFP, g.x, pPartA, gf0, bf0, bna0, bnc0);
    }
    cudaStreamWaitEvent(0, evEdge, 0);
    cudaStreamWaitEvent(0, evS, 0);
    k_gather_x0<<<N_QP / 2, 256>>>(bna0, bnc0, bna1, bnc1);

    {
        dim3 g((N_QP + 127) / 128, 2);
        k_mma<<<g, 256>>>(pX0H, pX0L, pW1H, pW1L, pY2, pPartA, N_QP, C1, C0);
        k_bnfinal<<<1, 1024>>>(C1, N_QP, g.x, pPartA, g1, beta1, bna2, bnc2);
    }
    k_bnrelu_split<<<(N_QP * C1 / 4 + 255) / 256, 256>>>(pY2, N_QP * C1 / 4, bna2, bnc2);

    {
        dim3 g((N_QP + 127) / 128, 2);
        k_mma<<<g, 256>>>(pX1H, pX1L, pW2H, pW2L, pY3, pPartA, N_QP, C1, C1);
        k_bnfinal<<<1, 1024>>>(C1, N_QP, g.x, pPartA, g2, beta2, bna3, bnc3);
    }
    k_bnrelu_out<<<(N_QP * C1 / 4 + 255) / 256, 256>>>(pY3, out, N_QP * C1 / 4, bna3, bnc3);
}

// round 17
// speedup vs baseline: 1.0908x; 1.0488x over previous
#include <cuda_runtime.h>
#include <cuda_bf16.h>
#include <math.h>
#include <cstdint>

#define N_QP   25000
#define N_REFP 50000
#define NEDGE  400000
#define C0     128
#define C1     256
#define BN_EPS 1e-5f

// ---------------- scratch ----------------
__device__ float d_w[NEDGE];
__device__ float d_wsum[N_QP];
__device__ int   d_deg[N_QP];
__device__ int   d_cursor[N_QP];
__device__ int   d_rowstart[N_QP + 1];
__device__ int   d_rsorted[NEDGE];
__device__ float d_wsorted[NEDGE];
__device__ float d_Y1[(size_t)N_REFP * C0];
__device__ float d_S [(size_t)N_QP * C0];
__device__ float d_Y2[(size_t)N_QP * C1];
__device__ float d_Y3[(size_t)N_QP * C1];
__device__ float d_partial[600 * 1024];      // region A @0, region B @400*1024
__device__ float d_bn[4][2][256];
__device__ __nv_bfloat16 d_refH[(size_t)N_REFP * C0], d_refL[(size_t)N_REFP * C0];
__device__ __nv_bfloat16 d_qH[(size_t)N_QP * C0],     d_qL[(size_t)N_QP * C0];
__device__ __nv_bfloat16 d_X0H[(size_t)N_QP * C0],    d_X0L[(size_t)N_QP * C0];
__device__ __nv_bfloat16 d_X1H[(size_t)N_QP * C1],    d_X1L[(size_t)N_QP * C1];
__device__ __nv_bfloat16 d_Wf0H[C0 * C0], d_Wf0L[C0 * C0];
__device__ __nv_bfloat16 d_Ws0H[C0 * C0], d_Ws0L[C0 * C0];
__device__ __nv_bfloat16 d_W1H[C0 * C1],  d_W1L[C0 * C1];
__device__ __nv_bfloat16 d_W2H[C1 * C1],  d_W2L[C1 * C1];

// ======================= helpers =======================
__device__ __forceinline__ uint32_t smem_u32(const void* p) {
    uint32_t a;
    asm("{ .reg .u64 t; cvta.to.shared.u64 t, %1; cvt.u32.u64 %0, t; }" : "=r"(a) : "l"(p));
    return a;
}
__device__ __forceinline__ void ldsm_x4(uint32_t& r0, uint32_t& r1, uint32_t& r2, uint32_t& r3,
                                        uint32_t addr) {
    asm volatile("ldmatrix.sync.aligned.m8n8.x4.shared.b16 {%0,%1,%2,%3}, [%4];"
                 : "=r"(r0), "=r"(r1), "=r"(r2), "=r"(r3) : "r"(addr));
}
__device__ __forceinline__ void ldsm_x4_t(uint32_t& r0, uint32_t& r1, uint32_t& r2, uint32_t& r3,
                                          uint32_t addr) {
    asm volatile("ldmatrix.sync.aligned.m8n8.x4.trans.shared.b16 {%0,%1,%2,%3}, [%4];"
                 : "=r"(r0), "=r"(r1), "=r"(r2), "=r"(r3) : "r"(addr));
}
__device__ __forceinline__ void mma_bf16(float* c, const uint32_t* a, const uint32_t* b) {
    asm volatile(
        "mma.sync.aligned.m16n8k16.row.col.f32.bf16.bf16.f32 "
        "{%0,%1,%2,%3}, {%4,%5,%6,%7}, {%8,%9}, {%0,%1,%2,%3};"
        : "+f"(c[0]), "+f"(c[1]), "+f"(c[2]), "+f"(c[3])
        : "r"(a[0]), "r"(a[1]), "r"(a[2]), "r"(a[3]), "r"(b[0]), "r"(b[1]));
}
__device__ __forceinline__ void cpa16(uint32_t dst, const void* src, int valid) {
    asm volatile("cp.async.cg.shared.global [%0], [%1], 16, %2;"
                 :: "r"(dst), "l"(src), "r"(valid ? 16 : 0) : "memory");
}
__device__ __forceinline__ void split2(float v, uint16_t& h, uint16_t& l) {
    __nv_bfloat16 bh = __float2bfloat16(v);
    __nv_bfloat16 bl = __float2bfloat16(v - __bfloat162float(bh));
    h = *(uint16_t*)&bh; l = *(uint16_t*)&bl;
}
__device__ __forceinline__ void split4_store(const float* X, uint16_t* H, uint16_t* L, int q) {
    float4 v = *(const float4*)(X + (size_t)q * 4);
    uint16_t h[4], l[4];
    split2(v.x, h[0], l[0]); split2(v.y, h[1], l[1]);
    split2(v.z, h[2], l[2]); split2(v.w, h[3], l[3]);
    *(uint2*)(H + (size_t)q * 4) = make_uint2(h[0] | ((uint32_t)h[1] << 16), h[2] | ((uint32_t)h[3] << 16));
    *(uint2*)(L + (size_t)q * 4) = make_uint2(l[0] | ((uint32_t)l[1] << 16), l[2] | ((uint32_t)l[3] << 16));
}

// ---------------- split kernels ----------------
#define QR  1600000
#define QQ  800000
#define QW0 4096
#define QW1 4096
#define QW2 8192
#define QW3 16384
#define QA_TOT (QR + QW0)
#define QB_TOT (QQ + QW1 + QW2 + QW3)
__global__ void k_split_a(const float* __restrict__ ref, const float* __restrict__ Wf0) {
    int i = blockIdx.x * blockDim.x + threadIdx.x;
    if (i >= QA_TOT) return;
    if (i < QR) { split4_store(ref, (uint16_t*)d_refH, (uint16_t*)d_refL, i); return; }
    i -= QR;
    split4_store(Wf0, (uint16_t*)d_Wf0H, (uint16_t*)d_Wf0L, i);
}
__global__ void k_split_b(const float* __restrict__ qf, const float* __restrict__ Ws0,
                          const float* __restrict__ W1, const float* __restrict__ W2) {
    int i = blockIdx.x * blockDim.x + threadIdx.x;
    if (i >= QB_TOT) return;
    if (i < QQ) { split4_store(qf, (uint16_t*)d_qH, (uint16_t*)d_qL, i); return; }
    i -= QQ;
    if (i < QW1) { split4_store(Ws0, (uint16_t*)d_Ws0H, (uint16_t*)d_Ws0L, i); return; }
    i -= QW1;
    if (i < QW2) { split4_store(W1, (uint16_t*)d_W1H, (uint16_t*)d_W1L, i); return; }
    i -= QW2;
    split4_store(W2, (uint16_t*)d_W2H, (uint16_t*)d_W2L, i);
}

// ---------------- init ----------------
__global__ void k_init() {
    int i = blockIdx.x * blockDim.x + threadIdx.x;
    if (i >= N_QP / 4 + 1) return;
    if (i * 4 + 3 < N_QP) {
        *(float4*)(d_wsum + i * 4) = make_float4(0.f, 0.f, 0.f, 0.f);
        *(int4*)(d_deg + i * 4) = make_int4(0, 0, 0, 0);
        *(int4*)(d_cursor + i * 4) = make_int4(0, 0, 0, 0);
    } else {
        for (int j = i * 4; j < N_QP; j++) { d_wsum[j] = 0.f; d_deg[j] = 0; d_cursor[j] = 0; }
    }
}

// ---------------- pipelined split-bf16 GEMM, term-reordered tile reuse ----------------
// Terms per K-chunk: (Ah,Bh), (Ah,Bl), (Al,Bh) — 4 tile loads/chunk instead of 6.
// Slots: Ah->A0 always, Al->A1 always; Bh_k->B[k&1], Bl_k->B[(k&1)^1].
#define KC 32
#define A_STRIDE 40
#define B_STRIDE 136
__global__ __launch_bounds__(256, 2)
void k_mma(const __nv_bfloat16* __restrict__ Ah, const __nv_bfloat16* __restrict__ Al,
           const __nv_bfloat16* __restrict__ Bh, const __nv_bfloat16* __restrict__ Bl,
           float* __restrict__ C, float* __restrict__ partial, int M, int N, int K) {
    __shared__ __align__(16) uint16_t sA[2][128 * A_STRIDE];
    __shared__ __align__(16) uint16_t sB[2][KC * B_STRIDE];
    __shared__ float sS[8][32], sS2[8][32];
    int tid = threadIdx.x, wid = tid >> 5, lane = tid & 31;
    int bm = blockIdx.x * 128, bn = blockIdx.y * 128;
    int wm = (wid & 1) * 64, wn = (wid >> 1) * 32;
    int mat = lane >> 3, r = lane & 7;
    int kpt = K >> 5;
    int nst = 3 * kpt;

    float acc[4][4][4];
    #pragma unroll
    for (int i = 0; i < 4; i++)
        #pragma unroll
        for (int j = 0; j < 4; j++)
            #pragma unroll
            for (int v = 0; v < 4; v++) acc[i][j][v] = 0.f;

    uint32_t aBase[2] = { smem_u32(sA[0]), smem_u32(sA[1]) };
    uint32_t bBase[2] = { smem_u32(sB[0]), smem_u32(sB[1]) };

    auto issueA = [&](const __nv_bfloat16* Ap, int koff, int slot) {
        #pragma unroll
        for (int i = 0; i < 2; i++) {
            int seg = i * 256 + tid;
            int row = seg >> 2, cs = (seg & 3) << 3;
            cpa16(aBase[slot] + (row * A_STRIDE + cs) * 2,
                  Ap + (size_t)(bm + row) * K + koff + cs, (bm + row) < M);
        }
    };
    auto issueB = [&](const __nv_bfloat16* Bp, int koff, int slot) {
        #pragma unroll
        for (int i = 0; i < 2; i++) {
            int seg = i * 256 + tid;
            int row = seg >> 4, cs = (seg & 15) << 3;
            cpa16(bBase[slot] + (row * B_STRIDE + cs) * 2,
                  Bp + (size_t)(koff + row) * N + bn + cs, 1);
        }
    };

    // prologue: stage 0 tiles (Ah_0 -> A0, Bh_0 -> B0)
    issueA(Ah, 0, 0);
    issueB(Bh, 0, 0);
    asm volatile("cp.async.commit_group;" ::: "memory");

    for (int s = 0; s < nst; s++) {
        int k = s / 3, t = s - 3 * k;
        if (s + 1 < nst) {
            int s1 = s + 1, k1 = s1 / 3, t1 = s1 - 3 * k1;
            if (t1 == 0) {                       // next chunk: Ah, Bh
                issueA(Ah, k1 << 5, 0);
                issueB(Bh, k1 << 5, k1 & 1);
            } else if (t1 == 1) {                // same chunk: Bl only
                issueB(Bl, k1 << 5, (k1 & 1) ^ 1);
            } else {                             // same chunk: Al only
                issueA(Al, k1 << 5, 1);
            }
            asm volatile("cp.async.commit_group;" ::: "memory");
            asm volatile("cp.async.wait_group 1;" ::: "memory");
        } else {
            asm volatile("cp.async.wait_group 0;" ::: "memory");
        }
        __syncthreads();
        int as = (t == 2) ? 1 : 0;
        int bs = (t == 1) ? ((k & 1) ^ 1) : (k & 1);
        #pragma unroll
        for (int ks = 0; ks < KC / 16; ks++) {
            uint32_t a[4][4], b[4][2];
            #pragma unroll
            for (int mt = 0; mt < 4; mt++) {
                int mrow = wm + mt * 16 + (mat & 1) * 8 + r;
                int kcol = ks * 16 + (mat >> 1) * 8;
                ldsm_x4(a[mt][0], a[mt][1], a[mt][2], a[mt][3],
                        aBase[as] + (mrow * A_STRIDE + kcol) * 2);
            }
            #pragma unroll
            for (int nt = 0; nt < 2; nt++) {
                int krow = ks * 16 + (mat & 1) * 8 + r;
                int ncol = wn + nt * 16 + (mat >> 1) * 8;
                ldsm_x4_t(b[nt * 2][0], b[nt * 2][1], b[nt * 2 + 1][0], b[nt * 2 + 1][1],
                          bBase[bs] + (krow * B_STRIDE + ncol) * 2);
            }
            #pragma unroll
            for (int mt = 0; mt < 4; mt++)
                #pragma unroll
                for (int nt = 0; nt < 4; nt++)
                    mma_bf16(acc[mt][nt], a[mt], b[nt]);
        }
        __syncthreads();
    }

    int g = lane >> 2, tg = lane & 3;
    #pragma unroll
    for (int mt = 0; mt < 4; mt++) {
        #pragma unroll
        for (int nt = 0; nt < 4; nt++) {
            int row0 = bm + wm + mt * 16 + g;
            int col = bn + wn + nt * 8 + tg * 2;
            if (row0 < M) {
                C[(size_t)row0 * N + col] = acc[mt][nt][0];
                C[(size_t)row0 * N + col + 1] = acc[mt][nt][1];
            }
            int row1 = row0 + 8;
            if (row1 < M) {
                C[(size_t)row1 * N + col] = acc[mt][nt][2];
                C[(size_t)row1 * N + col + 1] = acc[mt][nt][3];
            }
        }
    }

    // fused column stats (rows >= M contributed exact zeros)
    #pragma unroll
    for (int nt = 0; nt < 4; nt++) {
        #pragma unroll
        for (int p = 0; p < 2; p++) {
            float ss = 0.f, qq = 0.f;
            #pragma unroll
            for (int mt = 0; mt < 4; mt++) {
                float a0 = acc[mt][nt][p], a1 = acc[mt][nt][p + 2];
                ss += a0 + a1;
                qq += a0 * a0 + a1 * a1;
            }
            #pragma unroll
            for (int off = 16; off >= 4; off >>= 1) {
                ss += __shfl_down_sync(0xffffffff, ss, off);
                qq += __shfl_down_sync(0xffffffff, qq, off);
            }
            if (g == 0) {
                sS[wid][nt * 8 + tg * 2 + p] = ss;
                sS2[wid][nt * 8 + tg * 2 + p] = qq;
            }
        }
    }
    __syncthreads();
    if (tid < 128) {
        int w0 = (tid >> 5) * 2, lc = tid & 31;
        partial[blockIdx.x * 1024 + bn + tid] = sS[w0][lc] + sS[w0 + 1][lc];
        partial[blockIdx.x * 1024 + 512 + bn + tid] = sS2[w0][lc] + sS2[w0 + 1][lc];
    }
}

// ---------------- edge weights + degree histogram ----------------
__global__ void k_edge(const float4* __restrict__ ref_bxyz,
                       const float4* __restrict__ query_bxyz,
                       const int* __restrict__ e_ref,
                       const int* __restrict__ e_query) {
    int e = blockIdx.x * blockDim.x + threadIdx.x;
    if (e >= NEDGE) return;
    int r = e_ref[e], q = e_query[e];
    float4 rb = ref_bxyz[r];
    float4 qb = query_bxyz[q];
    float dx = rb.y - qb.y, dy = rb.z - qb.z, dz = rb.w - qb.w;
    float dist = sqrtf(dx * dx + dy * dy + dz * dz);
    float w = 1.0f / (dist + 1e-8f);
    d_w[e] = w;
    atomicAdd(&d_wsum[q], w);
    atomicAdd(&d_deg[q], 1);
}

// ---------------- single-pass scan ----------------
__global__ void k_scan() {
    __shared__ int wsum[32];
    const int CH = 25;
    int tid = threadIdx.x, lane = tid & 31, wid = tid >> 5;
    int base = tid * CH;
    int s = 0;
    #pragma unroll
    for (int i = 0; i < CH; i++) {
        int idx = base + i;
        if (idx < N_QP) s += d_deg[idx];
    }
    int v = s;
    #pragma unroll
    for (int off = 1; off < 32; off <<= 1) {
        int t = __shfl_up_sync(0xffffffff, v, off);
        if (lane >= off) v += t;
    }
    if (lane == 31) wsum[wid] = v;
    __syncthreads();
    if (wid == 0) {
        int w = wsum[lane];
        #pragma unroll
        for (int off = 1; off < 32; off <<= 1) {
            int t = __shfl_up_sync(0xffffffff, w, off);
            if (lane >= off) w += t;
        }
        wsum[lane] = w;
    }
    __syncthreads();
    int warp_excl = (wid == 0) ? 0 : wsum[wid - 1];
    int run = warp_excl + v - s;
    #pragma unroll
    for (int i = 0; i < CH; i++) {
        int idx = base + i;
        if (idx < N_QP) { d_rowstart[idx] = run; run += d_deg[idx]; }
    }
    if (base < N_QP && base + CH >= N_QP) d_rowstart[N_QP] = run;
}

// ---------------- bucket-fill: (ref_idx, weight) per slot ----------------
__global__ void k_fill(const int* __restrict__ e_query, const int* __restrict__ e_ref) {
    int e = blockIdx.x * blockDim.x + threadIdx.x;
    if (e >= NEDGE) return;
    int q = e_query[e];
    int pos = atomicAdd(&d_cursor[q], 1) + d_rowstart[q];
    d_rsorted[pos] = e_ref[e];
    d_wsorted[pos] = d_w[e];
}

// ---------------- BN finalize (parallel, 1024 threads) ----------------
__global__ void k_bnfinal(int C, int M, int NBLK, const float* __restrict__ partial,
                          const float* __restrict__ g, const float* __restrict__ b,
                          float* __restrict__ bna, float* __restrict__ bnc) {
    __shared__ float redS[4][256], redQ[4][256];
    int t = threadIdx.x;
    int c = t & 255, chunk = t >> 8;
    float s = 0.f, s2 = 0.f;
    for (int bx = chunk; bx < NBLK; bx += 4) {
        s += partial[bx * 1024 + c];
        s2 += partial[bx * 1024 + 512 + c];
    }
    redS[chunk][c] = s;
    redQ[chunk][c] = s2;
    __syncthreads();
    if (t < C) {
        float S = redS[0][t] + redS[1][t] + redS[2][t] + redS[3][t];
        float Q = redQ[0][t] + redQ[1][t] + redQ[2][t] + redQ[3][t];
        float m = S / (float)M;
        float v = Q / (float)M - m * m;
        float a = g[t] * rsqrtf(v + BN_EPS);
        bna[t] = a;
        bnc[t] = b[t] - a * m;
    }
}

// ---------------- fused gather + x0 ----------------
__global__ void k_gather_x0(const float* __restrict__ bna0, const float* __restrict__ bnc0,
                            const float* __restrict__ bna1, const float* __restrict__ bnc1) {
    __shared__ float sPart[4][128];
    int q = blockIdx.x;
    int tid = threadIdx.x, wid = tid >> 5, lane = tid & 31;
    int s = d_rowstart[q], t = d_rowstart[q + 1];
    float4 acc = make_float4(0.f, 0.f, 0.f, 0.f);
    for (int i = s + wid; i < t; i += 4) {
        int r = d_rsorted[i];
        float w = d_wsorted[i];
        float4 y = *(const float4*)(d_Y1 + (size_t)r * C0 + lane * 4);
        acc.x = fmaf(w, y.x, acc.x); acc.y = fmaf(w, y.y, acc.y);
        acc.z = fmaf(w, y.z, acc.z); acc.w = fmaf(w, y.w, acc.w);
    }
    sPart[wid][lane * 4 + 0] = acc.x;
    sPart[wid][lane * 4 + 1] = acc.y;
    sPart[wid][lane * 4 + 2] = acc.z;
    sPart[wid][lane * 4 + 3] = acc.w;
    __syncthreads();
    int c = tid;
    float sum = sPart[0][c] + sPart[1][c] + sPart[2][c] + sPart[3][c];
    float qf = 0.f;
    if (t > s) qf = bna0[c] * sum * (1.0f / d_wsum[q]) + bnc0[c];
    float sv = d_S[(size_t)q * C0 + c];
    float v = fmaxf(qf + bna1[c] * sv + bnc1[c], 0.f);
    uint16_t h, l;
    split2(v, h, l);
    ((uint16_t*)d_X0H)[(size_t)q * C0 + c] = h;
    ((uint16_t*)d_X0L)[(size_t)q * C0 + c] = l;
}

// ---------------- x1 = relu(a*Y + c), emit split bf16 (C=256) ----------------
__global__ void k_bnrelu_split(const float* __restrict__ Y, int n4,
                               const float* __restrict__ bna, const float* __restrict__ bnc) {
    int qd = blockIdx.x * blockDim.x + threadIdx.x;
    if (qd >= n4) return;
    int i = qd * 4;
    int c = i & 255;
    float4 y = *(float4*)(Y + i);
    float v0 = fmaxf(bna[c] * y.x + bnc[c], 0.f);
    float v1 = fmaxf(bna[c + 1] * y.y + bnc[c + 1], 0.f);
    float v2 = fmaxf(bna[c + 2] * y.z + bnc[c + 2], 0.f);
    float v3 = fmaxf(bna[c + 3] * y.w + bnc[c + 3], 0.f);
    uint16_t h[4], l[4];
    split2(v0, h[0], l[0]); split2(v1, h[1], l[1]);
    split2(v2, h[2], l[2]); split2(v3, h[3], l[3]);
    *(uint2*)((uint16_t*)d_X1H + i) = make_uint2(h[0] | ((uint32_t)h[1] << 16), h[2] | ((uint32_t)h[3] << 16));
    *(uint2*)((uint16_t*)d_X1L + i) = make_uint2(l[0] | ((uint32_t)l[1] << 16), l[2] | ((uint32_t)l[3] << 16));
}

// ---------------- out = relu(a*Y + c) fp32 (C=256) ----------------
__global__ void k_bnrelu_out(const float* __restrict__ Y, float* __restrict__ X, int n4,
                             const float* __restrict__ bna, const float* __restrict__ bnc) {
    int qd = blockIdx.x * blockDim.x + threadIdx.x;
    if (qd >= n4) return;
    int i = qd * 4;
    int c = i & 255;
    float4 y = *(float4*)(Y + i);
    float4 o;
    o.x = fmaxf(bna[c] * y.x + bnc[c], 0.f);
    o.y = fmaxf(bna[c + 1] * y.y + bnc[c + 1], 0.f);
    o.z = fmaxf(bna[c + 2] * y.z + bnc[c + 2], 0.f);
    o.w = fmaxf(bna[c + 3] * y.w + bnc[c + 3], 0.f);
    *(float4*)(X + i) = o;
}

// ---------------- launcher ----------------
extern "C" void kernel_launch(void* const* d_in, const int* in_sizes, int n_in,
                              void* d_out, int out_size) {
    const float* ref_bxyz   = (const float*)d_in[0];
    const float* ref_feat   = (const float*)d_in[1];
    const float* query_bxyz = (const float*)d_in[2];
    const float* query_feat = (const float*)d_in[3];
    const int*   e_ref      = (const int*)d_in[4];
    const int*   e_query    = (const int*)d_in[5];
    const float* Wf0   = (const float*)d_in[6];
    const float* gf0   = (const float*)d_in[7];
    const float* bf0   = (const float*)d_in[8];
    const float* Ws0   = (const float*)d_in[9];
    const float* gs0   = (const float*)d_in[10];
    const float* bs0   = (const float*)d_in[11];
    const float* W1    = (const float*)d_in[12];
    const float* g1    = (const float*)d_in[14];
    const float* beta1 = (const float*)d_in[15];
    const float* W2    = (const float*)d_in[16];
    const float* g2    = (const float*)d_in[18];
    const float* beta2 = (const float*)d_in[19];
    float* out = (float*)d_out;

    float *pY1, *pS, *pY2, *pY3, *pPart, *pBN;
    cudaGetSymbolAddress((void**)&pY1, d_Y1);
    cudaGetSymbolAddress((void**)&pS,  d_S);
    cudaGetSymbolAddress((void**)&pY2, d_Y2);
    cudaGetSymbolAddress((void**)&pY3, d_Y3);
    cudaGetSymbolAddress((void**)&pPart, d_partial);
    cudaGetSymbolAddress((void**)&pBN, d_bn);
    float* pPartA = pPart;
    float* pPartB = pPart + 400 * 1024;
    float* bna0 = pBN;            float* bnc0 = pBN + 256;
    float* bna1 = pBN + 512;      float* bnc1 = pBN + 768;
    float* bna2 = pBN + 1024;     float* bnc2 = pBN + 1280;
    float* bna3 = pBN + 1536;     float* bnc3 = pBN + 1792;

    __nv_bfloat16 *pRefH, *pRefL, *pQH, *pQL, *pX0H, *pX0L, *pX1H, *pX1L;
    __nv_bfloat16 *pWf0H, *pWf0L, *pWs0H, *pWs0L, *pW1H, *pW1L, *pW2H, *pW2L;
    cudaGetSymbolAddress((void**)&pRefH, d_refH); cudaGetSymbolAddress((void**)&pRefL, d_refL);
    cudaGetSymbolAddress((void**)&pQH, d_qH);     cudaGetSymbolAddress((void**)&pQL, d_qL);
    cudaGetSymbolAddress((void**)&pX0H, d_X0H);   cudaGetSymbolAddress((void**)&pX0L, d_X0L);
    cudaGetSymbolAddress((void**)&pX1H, d_X1H);   cudaGetSymbolAddress((void**)&pX1L, d_X1L);
    cudaGetSymbolAddress((void**)&pWf0H, d_Wf0H); cudaGetSymbolAddress((void**)&pWf0L, d_Wf0L);
    cudaGetSymbolAddress((void**)&pWs0H, d_Ws0H); cudaGetSymbolAddress((void**)&pWs0L, d_Ws0L);
    cudaGetSymbolAddress((void**)&pW1H, d_W1H);   cudaGetSymbolAddress((void**)&pW1L, d_W1L);
    cudaGetSymbolAddress((void**)&pW2H, d_W2H);   cudaGetSymbolAddress((void**)&pW2L, d_W2L);

    static cudaStream_t s1 = nullptr, s2 = nullptr;
    static cudaEvent_t evStart, evEdge, evS;
    if (!s1) {
        cudaStreamCreateWithFlags(&s1, cudaStreamNonBlocking);
        cudaStreamCreateWithFlags(&s2, cudaStreamNonBlocking);
        cudaEventCreateWithFlags(&evStart, cudaEventDisableTiming);
        cudaEventCreateWithFlags(&evEdge, cudaEventDisableTiming);
        cudaEventCreateWithFlags(&evS, cudaEventDisableTiming);
    }

    cudaEventRecord(evStart, 0);

    // s1: edge preprocessing (fully independent)
    cudaStreamWaitEvent(s1, evStart, 0);
    k_init<<<(N_QP / 4 + 256) / 256, 256, 0, s1>>>();
    k_edge<<<(NEDGE + 255) / 256, 256, 0, s1>>>((const float4*)ref_bxyz,
                                                (const float4*)query_bxyz, e_ref, e_query);
    k_scan<<<1, 1024, 0, s1>>>();
    k_fill<<<(NEDGE + 255) / 256, 256, 0, s1>>>(e_query, e_ref);
    cudaEventRecord(evEdge, s1);

    // s2: other splits + skip-branch GEMM + its BN finalize
    cudaStreamWaitEvent(s2, evStart, 0);
    k_split_b<<<(QB_TOT + 255) / 256, 256, 0, s2>>>(query_feat, Ws0, W1, W2);
    {
        dim3 g((N_QP + 127) / 128, 1);
        k_mma<<<g, 256, 0, s2>>>(pQH, pQL, pWs0H, pWs0L, pS, pPartB, N_QP, C0, C0);
        k_bnfinal<<<1, 1024, 0, s2>>>(C0, N_QP, g.x, pPartB, gs0, bs0, bna1, bnc1);
    }
    cudaEventRecord(evS, s2);

    // main chain
    k_split_a<<<(QA_TOT + 255) / 256, 256>>>(ref_feat, Wf0);
    {
        dim3 g((N_REFP + 127) / 128, 1);
        k_mma<<<g, 256>>>(pRefH, pRefL, pWf0H, pWf0L, pY1, pPartA, N_REFP, C0, C0);
        k_bnfinal<<<1, 1024>>>(C0, N_REFP, g.x, pPartA, gf0, bf0, bna0, bnc0);
    }
    cudaStreamWaitEvent(0, evEdge, 0);
    cudaStreamWaitEvent(0, evS, 0);
    k_gather_x0<<<N_QP, 128>>>(bna0, bnc0, bna1, bnc1);

    {
        dim3 g((N_QP + 127) / 128, 2);
        k_mma<<<g, 256>>>(pX0H, pX0L, pW1H, pW1L, pY2, pPartA, N_QP, C1, C0);
        k_bnfinal<<<1, 1024>>>(C1, N_QP, g.x, pPartA, g1, beta1, bna2, bnc2);
    }
    k_bnrelu_split<<<(N_QP * C1 / 4 + 255) / 256, 256>>>(pY2, N_QP * C1 / 4, bna2, bnc2);

    {
        dim3 g((N_QP + 127) / 128, 2);
        k_mma<<<g, 256>>>(pX1H, pX1L, pW2H, pW2L, pY3, pPartA, N_QP, C1, C1);
        k_bnfinal<<<1, 1024>>>(C1, N_QP, g.x, pPartA, g2, beta2, bna3, bnc3);
    }
    k_bnrelu_out<<<(N_QP * C1 / 4 + 255) / 256, 256>>>(pY3, out, N_QP * C1 / 4, bna3, bnc3);
}